// round 4
// baseline (speedup 1.0000x reference)
#include <cuda_runtime.h>
#include <math.h>

// Problem constants (fixed by the reference: B=16, D=256, K=64, H=W=96)
#define BD   16
#define DD   256
#define KK   64
#define NPIX 9216
#define CPAD 260          // C row pad in smem: keeps float4 alignment, spreads banks
#define NSPLIT 8

// Scratch (device globals; allocation is forbidden)
__device__ float g_A[(size_t)BD * NPIX * KK];   // softmax assignments [b][n][k], fp32
__device__ float g_sumA[BD * KK];               // column sums of A    [b][k]

// ---------------------------------------------------------------------------
// Kernel 0: zero output + g_sumA (d_out poisoned each replay; g_sumA persists)
// ---------------------------------------------------------------------------
__global__ void zero_kernel(float* __restrict__ E) {
    int i = blockIdx.x * 256 + threadIdx.x;   // grid covers B*K*D = 262144
    if (i < BD * KK * DD) E[i] = 0.0f;
    if (i < BD * KK)      g_sumA[i] = 0.0f;
}

// ---------------------------------------------------------------------------
// Kernel 1 (assign): per CTA 256 pixels. Thread t: kh = t&1 owns 32 of the 64
// codewords, pixel pair p, p+1 where p = nbase + (t>>1)*2. Computes dots,
// x^2, scaled L2, softmax (pair reduction via shfl_xor 1), writes A to g_A.
// ---------------------------------------------------------------------------
__global__ void __launch_bounds__(256, 2)
assign_kernel(const float* __restrict__ X, const float* __restrict__ Cw,
              const float* __restrict__ scale) {
    extern __shared__ float sm[];
    float* Cs  = sm;                 // [64][CPAD]
    float* c2s = sm + KK * CPAD;     // [64]
    float* scs = c2s + KK;           // [64]

    const int t = threadIdx.x;
    const int b = blockIdx.y;
    const int nbase = blockIdx.x << 8;

    // Stage codewords (coalesced along d)
    for (int i = t; i < KK * DD; i += 256)
        Cs[(i >> 8) * CPAD + (i & 255)] = Cw[i];
    if (t < KK) scs[t] = scale[t];
    __syncthreads();
    if (t < KK) {
        float s = 0.0f;
        #pragma unroll 8
        for (int d = 0; d < DD; ++d) { float c = Cs[t * CPAD + d]; s += c * c; }
        c2s[t] = s;
    }
    __syncthreads();

    const int kh    = t & 1;
    const int kbase = kh << 5;                 // 0 or 32
    const int p     = nbase + ((t >> 1) << 1); // pixel pair base
    const float* Xb = X + (size_t)b * DD * NPIX + p;

    float acc0[32], acc1[32];
    #pragma unroll
    for (int j = 0; j < 32; ++j) { acc0[j] = 0.0f; acc1[j] = 0.0f; }
    float x2a = 0.0f, x2b = 0.0f;

    for (int d = 0; d < DD; d += 4) {
        float2 xv0 = *reinterpret_cast<const float2*>(Xb + (size_t)(d + 0) * NPIX);
        float2 xv1 = *reinterpret_cast<const float2*>(Xb + (size_t)(d + 1) * NPIX);
        float2 xv2 = *reinterpret_cast<const float2*>(Xb + (size_t)(d + 2) * NPIX);
        float2 xv3 = *reinterpret_cast<const float2*>(Xb + (size_t)(d + 3) * NPIX);
        x2a += xv0.x * xv0.x + xv1.x * xv1.x + xv2.x * xv2.x + xv3.x * xv3.x;
        x2b += xv0.y * xv0.y + xv1.y * xv1.y + xv2.y * xv2.y + xv3.y * xv3.y;
        const float* crow = Cs + kbase * CPAD + d;
        #pragma unroll
        for (int j = 0; j < 32; ++j) {
            float4 c4 = *reinterpret_cast<const float4*>(crow + j * CPAD);
            acc0[j] += xv0.x * c4.x + xv1.x * c4.y + xv2.x * c4.z + xv3.x * c4.w;
            acc1[j] += xv0.y * c4.x + xv1.y * c4.y + xv2.y * c4.z + xv3.y * c4.w;
        }
    }

    // SL = scale_k * (x2 - 2*dot + c2_k); softmax over the full 64 (pairwise)
    float m0 = -1e30f, m1 = -1e30f;
    #pragma unroll
    for (int j = 0; j < 32; ++j) {
        const int k = kbase + j;
        const float sck = scs[k], c2k = c2s[k];
        float s0 = sck * (x2a - 2.0f * acc0[j] + c2k);
        float s1 = sck * (x2b - 2.0f * acc1[j] + c2k);
        acc0[j] = s0; acc1[j] = s1;
        m0 = fmaxf(m0, s0); m1 = fmaxf(m1, s1);
    }
    m0 = fmaxf(m0, __shfl_xor_sync(0xffffffffu, m0, 1));
    m1 = fmaxf(m1, __shfl_xor_sync(0xffffffffu, m1, 1));
    float s0 = 0.0f, s1 = 0.0f;
    #pragma unroll
    for (int j = 0; j < 32; ++j) {
        float e0 = __expf(acc0[j] - m0);
        float e1 = __expf(acc1[j] - m1);
        acc0[j] = e0; acc1[j] = e1;
        s0 += e0; s1 += e1;
    }
    s0 += __shfl_xor_sync(0xffffffffu, s0, 1);
    s1 += __shfl_xor_sync(0xffffffffu, s1, 1);
    const float r0 = 1.0f / s0, r1 = 1.0f / s1;

    float* A0 = g_A + ((size_t)b * NPIX + p) * KK + kbase;
    float* A1 = A0 + KK;
    #pragma unroll
    for (int j = 0; j < 32; j += 4) {
        *reinterpret_cast<float4*>(A0 + j) =
            make_float4(acc0[j] * r0, acc0[j + 1] * r0, acc0[j + 2] * r0, acc0[j + 3] * r0);
        *reinterpret_cast<float4*>(A1 + j) =
            make_float4(acc1[j] * r1, acc1[j + 1] * r1, acc1[j + 2] * r1, acc1[j + 3] * r1);
    }
}

// ---------------------------------------------------------------------------
// Kernel 2 (aggregate): E_partial[k, d-tile] = sum_n A[n,k] * X[d,n].
// Grid (dt=4, ns=8, b=16); 256 threads compute a 64k x 64d tile, 4x4/thread,
// streaming n in chunks of 32 through smem. sumA accumulated during staging.
// ---------------------------------------------------------------------------
__global__ void __launch_bounds__(256)
aggregate_kernel(const float* __restrict__ X, float* __restrict__ E) {
    __shared__ float As[32 * 68];   // [nn][k], padded row 68
    __shared__ float Xs[64 * 33];   // [d][nn], padded row 33

    const int t  = threadIdx.x;
    const int dt = blockIdx.x;      // 0..3  (d tile of 64)
    const int ns = blockIdx.y;      // 0..7  (n split)
    const int b  = blockIdx.z;
    const int ky = t & 15, dy = t >> 4;
    const int k0 = ky << 2, d0 = dy << 2;

    const float* Ab = g_A + (size_t)b * NPIX * KK;
    const float* Xb = X + (size_t)b * DD * NPIX + (size_t)dt * 64 * NPIX;
    const int nbeg = ns * (NPIX / NSPLIT);
    const int nend = nbeg + (NPIX / NSPLIT);

    float acc[16];
    #pragma unroll
    for (int i = 0; i < 16; ++i) acc[i] = 0.0f;
    float sA0 = 0.0f, sA1 = 0.0f, sA2 = 0.0f, sA3 = 0.0f;
    const int r0s = t >> 5, cc = t & 31;

    for (int n0 = nbeg; n0 < nend; n0 += 32) {
        // Stage A chunk: 32 rows of 64 = 2048 contiguous floats
        const float4* src = reinterpret_cast<const float4*>(Ab + (size_t)n0 * KK);
        float4 v0 = src[t];
        float4 v1 = src[t + 256];
        sA0 += v0.x + v1.x; sA1 += v0.y + v1.y;
        sA2 += v0.z + v1.z; sA3 += v0.w + v1.w;
        *reinterpret_cast<float4*>(&As[(t >> 4) * 68 + k0])        = v0;
        *reinterpret_cast<float4*>(&As[((t >> 4) + 16) * 68 + k0]) = v1;
        // Stage X chunk: 64 d-rows x 32 n (coalesced per row)
        #pragma unroll
        for (int i = 0; i < 8; ++i) {
            int r = r0s + (i << 3);
            Xs[r * 33 + cc] = Xb[(size_t)r * NPIX + n0 + cc];
        }
        __syncthreads();
        #pragma unroll
        for (int nn = 0; nn < 32; ++nn) {
            float4 a4 = *reinterpret_cast<const float4*>(&As[nn * 68 + k0]);
            float xr0 = Xs[(d0 + 0) * 33 + nn];
            float xr1 = Xs[(d0 + 1) * 33 + nn];
            float xr2 = Xs[(d0 + 2) * 33 + nn];
            float xr3 = Xs[(d0 + 3) * 33 + nn];
            acc[0]  += a4.x * xr0; acc[1]  += a4.x * xr1; acc[2]  += a4.x * xr2; acc[3]  += a4.x * xr3;
            acc[4]  += a4.y * xr0; acc[5]  += a4.y * xr1; acc[6]  += a4.y * xr2; acc[7]  += a4.y * xr3;
            acc[8]  += a4.z * xr0; acc[9]  += a4.z * xr1; acc[10] += a4.z * xr2; acc[11] += a4.z * xr3;
            acc[12] += a4.w * xr0; acc[13] += a4.w * xr1; acc[14] += a4.w * xr2; acc[15] += a4.w * xr3;
        }
        __syncthreads();
    }

    // Reduce sumA across the 16 dy-threads per k (only dt==0 commits it —
    // the A stream is identical across dt tiles).
    float* sr = As;   // reuse: 16*64 = 1024 floats
    sr[dy * 64 + k0 + 0] = sA0;
    sr[dy * 64 + k0 + 1] = sA1;
    sr[dy * 64 + k0 + 2] = sA2;
    sr[dy * 64 + k0 + 3] = sA3;
    __syncthreads();
    if (dt == 0 && t < 64) {
        float s = 0.0f;
        #pragma unroll
        for (int r = 0; r < 16; ++r) s += sr[r * 64 + t];
        atomicAdd(&g_sumA[b * KK + t], s);
    }

    float* Eb = E + (size_t)b * KK * DD + (size_t)dt * 64 + d0;
    #pragma unroll
    for (int j = 0; j < 4; ++j)
        #pragma unroll
        for (int i = 0; i < 4; ++i)
            atomicAdd(&Eb[(size_t)(k0 + j) * DD + i], acc[j * 4 + i]);
}

// ---------------------------------------------------------------------------
// Kernel 3 (finalize): E[b,k,d] -= sumA[b,k] * C[k,d]
// ---------------------------------------------------------------------------
__global__ void finalize_kernel(const float* __restrict__ Cw, float* __restrict__ E) {
    int idx = blockIdx.x * 256 + threadIdx.x;   // covers 262144
    if (idx >= BD * KK * DD) return;
    int kd = idx & (KK * DD - 1);   // k*256 + d
    int b  = idx >> 14;
    E[idx] -= g_sumA[(b << 6) + (kd >> 8)] * Cw[kd];
}

// ---------------------------------------------------------------------------
// Launch. Inputs per metadata order: X [16,256,96,96] f32, codewords [64,256]
// f32, scale [64] f32. Output E [16,64,256] f32.
// ---------------------------------------------------------------------------
extern "C" void kernel_launch(void* const* d_in, const int* in_sizes, int n_in,
                              void* d_out, int out_size) {
    const float* X     = (const float*)d_in[0];
    const float* Cw    = (const float*)d_in[1];
    const float* scale = (const float*)d_in[2];
    float* E = (float*)d_out;

    const int smem_assign = (KK * CPAD + 2 * KK) * (int)sizeof(float);  // 67072 B
    cudaFuncSetAttribute(assign_kernel,
                         cudaFuncAttributeMaxDynamicSharedMemorySize, smem_assign);

    zero_kernel<<<1024, 256>>>(E);
    assign_kernel<<<dim3(NPIX / 256, BD), 256, smem_assign>>>(X, Cw, scale);
    aggregate_kernel<<<dim3(4, NSPLIT, BD), 256>>>(X, E);
    finalize_kernel<<<1024, 256>>>(Cw, E);
}

// round 6
// speedup vs baseline: 1.6201x; 1.6201x over previous
#include <cuda_runtime.h>
#include <math.h>

// Problem constants (fixed by the reference: B=16, D=256, K=64, H=W=96)
#define BD   16
#define DD   256
#define KK   64
#define NPIX 9216
#define NS   18            // aggregate n-splits: 288 CTAs = 1 wave at occ 2

// Scratch (device globals; allocation is forbidden)
__device__ float g_A[(size_t)BD * NPIX * KK];   // softmax assignments [b][n][k]
__device__ float g_sumA[BD * KK];               // column sums of A    [b][k]

// ---- packed fp32x2 helpers (SASS FFMA2 path; fp32-exact) --------------------
__device__ __forceinline__ unsigned long long pack2(float lo, float hi) {
    unsigned long long r;
    asm("mov.b64 %0, {%1, %2};" : "=l"(r) : "f"(lo), "f"(hi));
    return r;
}
__device__ __forceinline__ void unpack2(unsigned long long v, float& lo, float& hi) {
    asm("mov.b64 {%0, %1}, %2;" : "=f"(lo), "=f"(hi) : "l"(v));
}
__device__ __forceinline__ void fma2(unsigned long long& d,
                                     unsigned long long a, unsigned long long b) {
    asm("fma.rn.f32x2 %0, %1, %2, %0;" : "+l"(d) : "l"(a), "l"(b));
}

// ---------------------------------------------------------------------------
// Kernel 0: zero output + g_sumA (d_out poisoned each replay; g_sumA persists)
// ---------------------------------------------------------------------------
__global__ void zero_kernel(float* __restrict__ E) {
    int i = blockIdx.x * 256 + threadIdx.x;   // covers B*K*D = 262144
    if (i < BD * KK * DD) E[i] = 0.0f;
    if (i < BD * KK)      g_sumA[i] = 0.0f;
}

// ---------------------------------------------------------------------------
// Kernel 1 (assign): 1 pixel/thread, all 64 codewords as 32 packed f32x2 accs.
// C staged in smem as k-pairs: Cp[j][d] = (C[2j][d], C[2j+1][d]). LDS.128
// fetches the pair for d and d+1 (pure broadcast). Softmax fully in-thread.
// ---------------------------------------------------------------------------
__global__ void __launch_bounds__(256, 2)
assign_kernel(const float* __restrict__ X, const float* __restrict__ Cw,
              const float* __restrict__ scale) {
    extern __shared__ float sm[];
    float2* Cp = reinterpret_cast<float2*>(sm);   // [32][256] float2 (64 KB)
    float* c2s = sm + 2 * 32 * 256;               // [64]
    float* scs = c2s + 64;                        // [64]

    const int t = threadIdx.x;
    const int b = blockIdx.y;

    // Stage C into paired layout (coalesced read; 2-way smem store conflict, one-time)
    for (int i = t; i < KK * DD; i += 256) {
        int k = i >> 8, d = i & 255;
        sm[((k >> 1) * 256 + d) * 2 + (k & 1)] = Cw[i];
    }
    if (t < KK) scs[t] = scale[t];
    __syncthreads();
    if (t < KK) {
        float s = 0.0f;
        const float* row = sm + (t >> 1) * 512 + (t & 1);
        #pragma unroll 8
        for (int d = 0; d < DD; ++d) { float c = row[2 * d]; s += c * c; }
        c2s[t] = s;
    }
    __syncthreads();

    const int p = (blockIdx.x << 8) + t;
    const float* Xp = X + (size_t)b * DD * NPIX + p;

    unsigned long long acc[32];
    #pragma unroll
    for (int j = 0; j < 32; ++j) acc[j] = 0ull;
    float x2 = 0.0f;

    // Main loop: 2 d per iteration, prefetch next pair of x values
    float xc0 = Xp[0];
    float xc1 = Xp[NPIX];
    for (int d = 0; d < DD; d += 2) {
        float xn0 = 0.0f, xn1 = 0.0f;
        if (d + 2 < DD) {
            xn0 = Xp[(size_t)(d + 2) * NPIX];
            xn1 = Xp[(size_t)(d + 3) * NPIX];
        }
        const unsigned long long s0 = pack2(xc0, xc0);
        const unsigned long long s1 = pack2(xc1, xc1);
        x2 += xc0 * xc0;
        x2 += xc1 * xc1;
        const ulonglong2* cr = reinterpret_cast<const ulonglong2*>(Cp + d);
        #pragma unroll
        for (int j = 0; j < 32; ++j) {
            ulonglong2 cv = cr[j * 128];   // (pair@d, pair@d+1), broadcast LDS.128
            fma2(acc[j], s0, cv.x);
            fma2(acc[j], s1, cv.y);
        }
        xc0 = xn0; xc1 = xn1;
    }

    // SL = scale_k * (x2 - 2*dot + c2_k); softmax over 64 entirely in-thread.
    // Repack into acc[] to keep register count under the occ-2 budget.
    float m = -1e30f;
    #pragma unroll
    for (int j = 0; j < 32; ++j) {
        float d0, d1; unpack2(acc[j], d0, d1);
        const int k = 2 * j;
        float s0 = scs[k]     * (x2 - 2.0f * d0 + c2s[k]);
        float s1 = scs[k + 1] * (x2 - 2.0f * d1 + c2s[k + 1]);
        acc[j] = pack2(s0, s1);
        m = fmaxf(m, fmaxf(s0, s1));
    }
    float ssum = 0.0f;
    #pragma unroll
    for (int j = 0; j < 32; ++j) {
        float s0, s1; unpack2(acc[j], s0, s1);
        float e0 = __expf(s0 - m), e1 = __expf(s1 - m);
        acc[j] = pack2(e0, e1);
        ssum += e0 + e1;
    }
    const float r = 1.0f / ssum;

    float* Ap = g_A + ((size_t)b * NPIX + p) * KK;
    #pragma unroll
    for (int j = 0; j < 32; j += 2) {
        float e0, e1, e2, e3;
        unpack2(acc[j],     e0, e1);
        unpack2(acc[j + 1], e2, e3);
        *reinterpret_cast<float4*>(Ap + 2 * j) =
            make_float4(e0 * r, e1 * r, e2 * r, e3 * r);
    }
}

// ---------------------------------------------------------------------------
// Kernel 2 (aggregate): E[b,k,d] partial = sum_n A[n,k]*X[d,n], packed over k.
// CTA = full 64k x 256d tile, thread = 8k x 8d (32 f32x2 accs, pairs along k).
// A pairs come straight out of LDS.128 (k-contiguous) — zero pack overhead.
// Grid (ns=18, b=16); sumA accumulated during A staging.
// ---------------------------------------------------------------------------
__global__ void __launch_bounds__(256, 2)
aggregate_kernel(const float* __restrict__ X, float* __restrict__ E) {
    __shared__ float As[32 * 68];    // [nn][k], padded row 68
    __shared__ float Xs[256 * 33];   // [d][nn], padded row 33

    const int t  = threadIdx.x;
    const int ns = blockIdx.x;       // 0..17
    const int b  = blockIdx.y;
    const int ky = t & 7,  dy = t >> 3;
    const int k0 = ky << 3, d0 = dy << 3;

    const float* Ab = g_A + (size_t)b * NPIX * KK;
    const float* Xb = X + (size_t)b * DD * NPIX;
    const int nbeg = ns * (NPIX / NS);           // 512 pixels per CTA

    unsigned long long acc[32];
    #pragma unroll
    for (int i = 0; i < 32; ++i) acc[i] = 0ull;
    float sA0 = 0.0f, sA1 = 0.0f, sA2 = 0.0f, sA3 = 0.0f;
    const int r0s = t >> 5, cc = t & 31;
    const int sk0 = (t & 15) << 2;

    for (int c0 = 0; c0 < NPIX / NS; c0 += 32) {
        const int n0 = nbeg + c0;
        // Stage A chunk (32 rows x 64 = 2048 contiguous floats) + sumA partials
        const float4* src = reinterpret_cast<const float4*>(Ab + (size_t)n0 * KK);
        float4 v0 = src[t];
        float4 v1 = src[t + 256];
        sA0 += v0.x + v1.x; sA1 += v0.y + v1.y;
        sA2 += v0.z + v1.z; sA3 += v0.w + v1.w;
        *reinterpret_cast<float4*>(&As[(t >> 4) * 68 + sk0])        = v0;
        *reinterpret_cast<float4*>(&As[((t >> 4) + 16) * 68 + sk0]) = v1;
        // Stage X chunk: 256 d-rows x 32 n (coalesced rows, conflict-free STS)
        #pragma unroll
        for (int i = 0; i < 32; ++i) {
            int rr = r0s + (i << 3);
            Xs[rr * 33 + cc] = Xb[(size_t)rr * NPIX + n0 + cc];
        }
        __syncthreads();
        #pragma unroll
        for (int nn = 0; nn < 32; ++nn) {
            ulonglong2 a01 = *reinterpret_cast<const ulonglong2*>(&As[nn * 68 + k0]);
            ulonglong2 a23 = *reinterpret_cast<const ulonglong2*>(&As[nn * 68 + k0 + 4]);
            #pragma unroll
            for (int i = 0; i < 8; ++i) {
                float xv = Xs[(d0 + i) * 33 + nn];
                unsigned long long xs = pack2(xv, xv);
                fma2(acc[i],      a01.x, xs);
                fma2(acc[8 + i],  a01.y, xs);
                fma2(acc[16 + i], a23.x, xs);
                fma2(acc[24 + i], a23.y, xs);
            }
        }
        __syncthreads();
    }

    // sumA: reduce the 16 partials per k across threads, commit via atomic
    float* sr = As;   // reuse (16*64 = 1024 floats)
    sr[(t >> 4) * 64 + sk0 + 0] = sA0;
    sr[(t >> 4) * 64 + sk0 + 1] = sA1;
    sr[(t >> 4) * 64 + sk0 + 2] = sA2;
    sr[(t >> 4) * 64 + sk0 + 3] = sA3;
    __syncthreads();
    if (t < 64) {
        float s = 0.0f;
        #pragma unroll
        for (int rr = 0; rr < 16; ++rr) s += sr[rr * 64 + t];
        atomicAdd(&g_sumA[b * KK + t], s);
    }

    float* Eb = E + (size_t)b * KK * DD;
    #pragma unroll
    for (int jp = 0; jp < 4; ++jp)
        #pragma unroll
        for (int i = 0; i < 8; ++i) {
            float lo, hi;
            unpack2(acc[jp * 8 + i], lo, hi);
            atomicAdd(&Eb[(size_t)(k0 + 2 * jp)     * DD + d0 + i], lo);
            atomicAdd(&Eb[(size_t)(k0 + 2 * jp + 1) * DD + d0 + i], hi);
        }
}

// ---------------------------------------------------------------------------
// Kernel 3 (finalize): E[b,k,d] -= sumA[b,k] * C[k,d]
// ---------------------------------------------------------------------------
__global__ void finalize_kernel(const float* __restrict__ Cw, float* __restrict__ E) {
    int idx = blockIdx.x * 256 + threadIdx.x;   // covers 262144
    if (idx >= BD * KK * DD) return;
    int kd = idx & (KK * DD - 1);   // k*256 + d
    int b  = idx >> 14;
    E[idx] -= g_sumA[(b << 6) + (kd >> 8)] * Cw[kd];
}

// ---------------------------------------------------------------------------
// Launch. Inputs: X [16,256,96,96] f32, codewords [64,256] f32, scale [64] f32.
// Output E [16,64,256] f32.
// ---------------------------------------------------------------------------
extern "C" void kernel_launch(void* const* d_in, const int* in_sizes, int n_in,
                              void* d_out, int out_size) {
    const float* X     = (const float*)d_in[0];
    const float* Cw    = (const float*)d_in[1];
    const float* scale = (const float*)d_in[2];
    float* E = (float*)d_out;

    const int smem_assign = (2 * 32 * 256 + 2 * KK) * (int)sizeof(float);  // 66048 B
    cudaFuncSetAttribute(assign_kernel,
                         cudaFuncAttributeMaxDynamicSharedMemorySize, smem_assign);

    zero_kernel<<<1024, 256>>>(E);
    assign_kernel<<<dim3(NPIX / 256, BD), 256, smem_assign>>>(X, Cw, scale);
    aggregate_kernel<<<dim3(NS, BD), 256>>>(X, E);
    finalize_kernel<<<1024, 256>>>(Cw, E);
}

// round 9
// speedup vs baseline: 1.6704x; 1.0311x over previous
#include <cuda_runtime.h>
#include <math.h>

// Problem constants: B=16, D=256, K=64, H=W=96 -> N=9216
#define BD   16
#define DD   256
#define KK   64
#define NPIX 9216

// Scratch (device globals; allocation is forbidden)
__device__ float g_A[(size_t)BD * NPIX * KK];   // softmax weights [b][n][k]
__device__ float g_sumA[BD * KK];               // column sums of A

// ---- tf32 helpers ----------------------------------------------------------
__device__ __forceinline__ unsigned int f2tf32(float x) {
    unsigned int u;
    asm("cvt.rna.tf32.f32 %0, %1;" : "=r"(u) : "f"(x));
    return u;
}
// D(16x8,f32) += A(16x8,tf32,row) * B(8x8,tf32,col)
__device__ __forceinline__ void mma_tf32(float* c, const unsigned int* a,
                                         const unsigned int* b) {
    asm("mma.sync.aligned.m16n8k8.row.col.f32.tf32.tf32.f32 "
        "{%0,%1,%2,%3}, {%4,%5,%6,%7}, {%8,%9}, {%0,%1,%2,%3};"
        : "+f"(c[0]), "+f"(c[1]), "+f"(c[2]), "+f"(c[3])
        : "r"(a[0]), "r"(a[1]), "r"(a[2]), "r"(a[3]), "r"(b[0]), "r"(b[1]));
}

// ---------------------------------------------------------------------------
// Kernel 0: zero output + g_sumA (d_out poisoned each replay; g_sumA persists)
// ---------------------------------------------------------------------------
__global__ void zero_kernel(float* __restrict__ E) {
    int i = blockIdx.x * 256 + threadIdx.x;
    if (i < BD * KK * DD) E[i] = 0.0f;
    if (i < BD * KK)      g_sumA[i] = 0.0f;
}

// ---------------------------------------------------------------------------
// Kernel 1 (assign): per CTA a 128-pixel tile. tf32 MMA computes xc[n,k];
// x2 kept exact fp32 (accumulated at staging); softmax on register fragments.
// SMEM float offsets:
//   CS 0      : C tf32 [64][260]   (16640)
//   XS 16640  : X tf32 [64][136]   (8704)   — 4 d-chunks, reused
//   C2 25344  : [64],  SC 25408 : [64]
//   X2 25472  : [256]  (x2 halves, n and n+128 partials by d-parity)
//   RM 25728  : [2][128], RS 25984 : [2][128]
// total 26240 floats = 104960 B  -> occupancy 2
// ---------------------------------------------------------------------------
#define CS_OFF 0
#define XS_OFF 16640
#define C2_OFF 25344
#define SC_OFF 25408
#define X2_OFF 25472
#define RM_OFF 25728
#define RS_OFF 25984
#define SM1_BYTES (26240 * 4)

__global__ void __launch_bounds__(256, 2)
assign_kernel(const float* __restrict__ X, const float* __restrict__ Cw,
              const float* __restrict__ scale) {
    extern __shared__ float sm[];
    unsigned int* smU = reinterpret_cast<unsigned int*>(sm);
    const int t = threadIdx.x;
    const int lane = t & 31, w = t >> 5;
    const int g = lane >> 2, tg = lane & 3;      // groupID, threadID-in-group
    const int b = blockIdx.y;
    const int n0 = blockIdx.x << 7;

    // Stage C as tf32 (coalesced) + scale
    #pragma unroll 4
    for (int i = 0; i < 64; ++i) {
        int idx = t + (i << 8);
        int k = idx >> 8, d = idx & 255;
        smU[CS_OFF + k * 260 + d] = f2tf32(Cw[idx]);
    }
    if (t < 64) sm[SC_OFF + t] = scale[t];
    __syncthreads();
    if (t < 64) {                                 // c2 (tiny term; tf32-exactness fine)
        float s = 0.0f;
        #pragma unroll 8
        for (int d = 0; d < 256; ++d) {
            float c = __uint_as_float(smU[CS_OFF + t * 260 + d]);
            s += c * c;
        }
        sm[C2_OFF + t] = s;
    }

    const int n0w = (w & 3) << 5;     // warp tile: 32 n
    const int k0w = (w >> 2) << 5;    //            x 32 k

    float acc[2][4][4];
    #pragma unroll
    for (int m = 0; m < 2; ++m)
        #pragma unroll
        for (int kt = 0; kt < 4; ++kt)
            #pragma unroll
            for (int j = 0; j < 4; ++j) acc[m][kt][j] = 0.0f;
    float x2p = 0.0f;

    const float* Xg = X + (size_t)b * DD * NPIX + n0;

    for (int ch = 0; ch < 4; ++ch) {              // 4 d-chunks of 64
        __syncthreads();                          // Xs free of prior readers
        #pragma unroll 4
        for (int i = 0; i < 32; ++i) {            // stage X chunk (+ exact x2)
            int idx = t + (i << 8);
            int dl = idx >> 7, n = idx & 127;     // n == t&127 (invariant)
            float v = Xg[(size_t)((ch << 6) + dl) * NPIX + n];
            x2p += v * v;
            smU[XS_OFF + dl * 136 + n] = f2tf32(v);
        }
        __syncthreads();
        #pragma unroll
        for (int dd = 0; dd < 64; dd += 8) {      // 8 K-steps per chunk
            unsigned int afr[2][4], bfr[4][2];
            #pragma unroll
            for (int m = 0; m < 2; ++m)
                #pragma unroll
                for (int i = 0; i < 4; ++i)
                    afr[m][i] = smU[XS_OFF + (dd + tg + ((i >> 1) << 2)) * 136
                                    + n0w + (m << 4) + g + ((i & 1) << 3)];
            #pragma unroll
            for (int kt = 0; kt < 4; ++kt)
                #pragma unroll
                for (int j = 0; j < 2; ++j)
                    bfr[kt][j] = smU[CS_OFF + (k0w + (kt << 3) + g) * 260
                                     + (ch << 6) + dd + tg + (j << 2)];
            #pragma unroll
            for (int m = 0; m < 2; ++m)
                #pragma unroll
                for (int kt = 0; kt < 4; ++kt)
                    mma_tf32(acc[m][kt], afr[m], bfr[kt]);
        }
    }
    sm[X2_OFF + t] = x2p;
    __syncthreads();

    // ---- epilogue: logits + softmax on fragments ----
    int   rows[2][2];
    float x2v[2][2];
    #pragma unroll
    for (int m = 0; m < 2; ++m)
        #pragma unroll
        for (int jr = 0; jr < 2; ++jr) {
            int r = n0w + (m << 4) + (jr << 3) + g;
            rows[m][jr] = r;
            x2v[m][jr]  = sm[X2_OFF + r] + sm[X2_OFF + r + 128];
        }
    float scv[4][2], c2v[4][2];
    #pragma unroll
    for (int kt = 0; kt < 4; ++kt)
        #pragma unroll
        for (int j = 0; j < 2; ++j) {
            int k = k0w + (kt << 3) + (tg << 1) + j;
            scv[kt][j] = sm[SC_OFF + k];
            c2v[kt][j] = sm[C2_OFF + k];
        }
    float rmax[2][2] = {{-1e30f, -1e30f}, {-1e30f, -1e30f}};
    #pragma unroll
    for (int m = 0; m < 2; ++m)
        #pragma unroll
        for (int kt = 0; kt < 4; ++kt)
            #pragma unroll
            for (int j = 0; j < 4; ++j) {
                float l = scv[kt][j & 1] *
                          (x2v[m][j >> 1] - 2.0f * acc[m][kt][j] + c2v[kt][j & 1]);
                acc[m][kt][j] = l;
                rmax[m][j >> 1] = fmaxf(rmax[m][j >> 1], l);
            }
    #pragma unroll
    for (int m = 0; m < 2; ++m)
        #pragma unroll
        for (int jr = 0; jr < 2; ++jr) {
            float v = rmax[m][jr];
            v = fmaxf(v, __shfl_xor_sync(0xffffffffu, v, 1));
            v = fmaxf(v, __shfl_xor_sync(0xffffffffu, v, 2));
            rmax[m][jr] = v;
        }
    const int kh = w >> 2;
    if (tg == 0)
        #pragma unroll
        for (int m = 0; m < 2; ++m)
            #pragma unroll
            for (int jr = 0; jr < 2; ++jr)
                sm[RM_OFF + (kh << 7) + rows[m][jr]] = rmax[m][jr];
    __syncthreads();
    #pragma unroll
    for (int m = 0; m < 2; ++m)
        #pragma unroll
        for (int jr = 0; jr < 2; ++jr)
            rmax[m][jr] = fmaxf(rmax[m][jr],
                                sm[RM_OFF + ((1 - kh) << 7) + rows[m][jr]]);
    float rsum[2][2] = {{0.0f, 0.0f}, {0.0f, 0.0f}};
    #pragma unroll
    for (int m = 0; m < 2; ++m)
        #pragma unroll
        for (int kt = 0; kt < 4; ++kt)
            #pragma unroll
            for (int j = 0; j < 4; ++j) {
                float e = __expf(acc[m][kt][j] - rmax[m][j >> 1]);
                acc[m][kt][j] = e;
                rsum[m][j >> 1] += e;
            }
    #pragma unroll
    for (int m = 0; m < 2; ++m)
        #pragma unroll
        for (int jr = 0; jr < 2; ++jr) {
            float v = rsum[m][jr];
            v += __shfl_xor_sync(0xffffffffu, v, 1);
            v += __shfl_xor_sync(0xffffffffu, v, 2);
            rsum[m][jr] = v;
        }
    if (tg == 0)
        #pragma unroll
        for (int m = 0; m < 2; ++m)
            #pragma unroll
            for (int jr = 0; jr < 2; ++jr)
                sm[RS_OFF + (kh << 7) + rows[m][jr]] = rsum[m][jr];
    __syncthreads();
    float* Ab = g_A + ((size_t)b * NPIX + n0) * 64;
    #pragma unroll
    for (int m = 0; m < 2; ++m)
        #pragma unroll
        for (int jr = 0; jr < 2; ++jr) {
            float inv = 1.0f / (rsum[m][jr] +
                                sm[RS_OFF + ((1 - kh) << 7) + rows[m][jr]]);
            #pragma unroll
            for (int kt = 0; kt < 4; ++kt) {
                float2 v = make_float2(acc[m][kt][(jr << 1)]     * inv,
                                       acc[m][kt][(jr << 1) + 1] * inv);
                *reinterpret_cast<float2*>(Ab + (size_t)rows[m][jr] * 64
                                           + k0w + (kt << 3) + (tg << 1)) = v;
            }
        }
}

// ---------------------------------------------------------------------------
// Kernel 2 (aggregate): E[b,k,d] = sum_n W[n,k]*X[d,n] via tf32 MMA.
// Grid (9,16): each CTA owns 1024 pixels, keeps the full 64x256 E partial in
// registers (warp tile 32k x 64d), commits with ONE atomic pass.
// SMEM uint offsets: XS2 0 [256][36]=9216, WS2 9216 [32][72]=2304 -> 46080 B
// ---------------------------------------------------------------------------
#define XS2_OFF 0
#define WS2_OFF 9216
#define SM2_BYTES (11520 * 4)

__global__ void __launch_bounds__(256, 2)
aggregate_kernel(const float* __restrict__ X, float* __restrict__ E) {
    extern __shared__ float sm2[];
    unsigned int* smU = reinterpret_cast<unsigned int*>(sm2);
    const int t = threadIdx.x;
    const int lane = t & 31, w = t >> 5;
    const int g = lane >> 2, tg = lane & 3;
    const int b = blockIdx.y;
    const int gn0 = blockIdx.x << 10;
    const int k0 = (w & 1) << 5, d0 = (w >> 1) << 6;

    float acc[2][8][4];
    #pragma unroll
    for (int m = 0; m < 2; ++m)
        #pragma unroll
        for (int dt = 0; dt < 8; ++dt)
            #pragma unroll
            for (int j = 0; j < 4; ++j) acc[m][dt][j] = 0.0f;
    float sAp = 0.0f;

    const float* Xg = X + (size_t)b * DD * NPIX + gn0;
    const float* Ag = g_A + ((size_t)b * NPIX + gn0) * 64;

    for (int c = 0; c < 32; ++c) {               // 32 n-chunks of 32
        if (c) __syncthreads();
        #pragma unroll
        for (int i = 0; i < 8; ++i) {            // stage W chunk (+sumA, k=t&63)
            int idx = t + (i << 8);
            int nl = idx >> 6, k = idx & 63;
            float v = Ag[(size_t)((c << 5) + nl) * 64 + k];
            sAp += v;
            smU[WS2_OFF + nl * 72 + k] = f2tf32(v);
        }
        #pragma unroll 4
        for (int i = 0; i < 32; ++i) {           // stage X chunk
            int idx = t + (i << 8);
            int d = idx >> 5, nn = idx & 31;
            smU[XS2_OFF + d * 36 + nn] =
                f2tf32(Xg[(size_t)d * NPIX + (c << 5) + nn]);
        }
        __syncthreads();
        #pragma unroll
        for (int ns = 0; ns < 32; ns += 8) {     // 4 K-steps over n
            unsigned int afr[2][4], bfr[8][2];
            #pragma unroll
            for (int m = 0; m < 2; ++m)
                #pragma unroll
                for (int i = 0; i < 4; ++i)
                    afr[m][i] = smU[WS2_OFF + (ns + tg + ((i >> 1) << 2)) * 72
                                    + k0 + (m << 4) + g + ((i & 1) << 3)];
            #pragma unroll
            for (int dt = 0; dt < 8; ++dt)
                #pragma unroll
                for (int j = 0; j < 2; ++j)
                    bfr[dt][j] = smU[XS2_OFF + (d0 + (dt << 3) + g) * 36
                                     + ns + tg + (j << 2)];
            #pragma unroll
            for (int m = 0; m < 2; ++m)
                #pragma unroll
                for (int dt = 0; dt < 8; ++dt)
                    mma_tf32(acc[m][dt], afr[m], bfr[dt]);
        }
    }
    __syncthreads();
    sm2[t] = sAp;                                 // reuse smem for sumA reduce
    __syncthreads();
    if (t < 64) {
        float s = sm2[t] + sm2[t + 64] + sm2[t + 128] + sm2[t + 192];
        atomicAdd(&g_sumA[(b << 6) + t], s);
    }

    float* Eb = E + (size_t)b * KK * DD;
    #pragma unroll
    for (int m = 0; m < 2; ++m)
        #pragma unroll
        for (int dt = 0; dt < 8; ++dt)
            #pragma unroll
            for (int j = 0; j < 4; ++j) {
                int k = k0 + (m << 4) + g + ((j >> 1) << 3);
                int d = d0 + (dt << 3) + (tg << 1) + (j & 1);
                atomicAdd(&Eb[(size_t)k * DD + d], acc[m][dt][j]);
            }
}

// ---------------------------------------------------------------------------
// Kernel 3 (finalize): E[b,k,d] -= sumA[b,k] * C[k,d]   (exact fp32)
// ---------------------------------------------------------------------------
__global__ void finalize_kernel(const float* __restrict__ Cw, float* __restrict__ E) {
    int idx = blockIdx.x * 256 + threadIdx.x;
    if (idx >= BD * KK * DD) return;
    int kd = idx & (KK * DD - 1);
    int b  = idx >> 14;
    E[idx] -= g_sumA[(b << 6) + (kd >> 8)] * Cw[kd];
}

// ---------------------------------------------------------------------------
// Launch. Inputs: X [16,256,96,96] f32, codewords [64,256] f32, scale [64] f32.
// Output E [16,64,256] f32.
// ---------------------------------------------------------------------------
extern "C" void kernel_launch(void* const* d_in, const int* in_sizes, int n_in,
                              void* d_out, int out_size) {
    const float* X     = (const float*)d_in[0];
    const float* Cw    = (const float*)d_in[1];
    const float* scale = (const float*)d_in[2];
    float* E = (float*)d_out;

    cudaFuncSetAttribute(assign_kernel,
                         cudaFuncAttributeMaxDynamicSharedMemorySize, SM1_BYTES);
    cudaFuncSetAttribute(aggregate_kernel,
                         cudaFuncAttributeMaxDynamicSharedMemorySize, SM2_BYTES);

    zero_kernel<<<1024, 256>>>(E);
    assign_kernel<<<dim3(NPIX / 128, BD), 256, SM1_BYTES>>>(X, Cw, scale);
    aggregate_kernel<<<dim3(9, BD), 256, SM2_BYTES>>>(X, E);
    finalize_kernel<<<1024, 256>>>(Cw, E);
}

// round 10
// speedup vs baseline: 3.2680x; 1.9564x over previous
#include <cuda_runtime.h>
#include <math.h>

// Problem constants: B=16, D=256, K=64, H=W=96 -> N=9216
#define BD   16
#define DD   256
#define KK   64
#define NPIX 9216

// Scratch (device global; allocation is forbidden). g_A is GONE (fused).
__device__ float g_sumA[BD * KK];

// ---- tf32 helpers ----------------------------------------------------------
__device__ __forceinline__ unsigned int f2tf32(float x) {
    unsigned int u;
    asm("cvt.rna.tf32.f32 %0, %1;" : "=r"(u) : "f"(x));
    return u;
}
// D(16x8,f32) += A(16x8,tf32,row) * B(8x8,tf32,col)
__device__ __forceinline__ void mma_tf32(float* c, const unsigned int* a,
                                         const unsigned int* b) {
    asm("mma.sync.aligned.m16n8k8.row.col.f32.tf32.tf32.f32 "
        "{%0,%1,%2,%3}, {%4,%5,%6,%7}, {%8,%9}, {%0,%1,%2,%3};"
        : "+f"(c[0]), "+f"(c[1]), "+f"(c[2]), "+f"(c[3])
        : "r"(a[0]), "r"(a[1]), "r"(a[2]), "r"(a[3]), "r"(b[0]), "r"(b[1]));
}

// ---------------------------------------------------------------------------
// Kernel 0: zero output + g_sumA (d_out poisoned each replay; g_sumA persists)
// ---------------------------------------------------------------------------
__global__ void zero_kernel(float* __restrict__ E) {
    int i = blockIdx.x * 256 + threadIdx.x;
    if (i < BD * KK * DD) E[i] = 0.0f;
    if (i < BD * KK)      g_sumA[i] = 0.0f;
}

// ---------------------------------------------------------------------------
// Fused kernel: per CTA 1024 pixels of one batch. C resident in smem.
// Chunk loop (16 x 64 pixels): stage X once -> MMA1 (S = X.C^T, K=256)
// -> fragment softmax -> W to smem -> MMA2 (E += W^T.X, K=64) into a
// register-resident 64k x 256d E tile. One atomic pass at the end.
//
// SMEM float offsets:
//   CS 0     : C tf32 [64][260]      (16640)
//   XS 16640 : X tf32 [256][68]      (17408)
//   WS 34048 : W tf32 [64][68]       (4352)
//   SC 38400 [64], C2 38464 [64], X2P 38528 [256],
//   RM 38784 [128], RS 38912 [128], SA 39040 [64]
// total 39104 floats = 156416 B -> occupancy 1
// ---------------------------------------------------------------------------
#define CS_OFF   0
#define XS_OFF   16640
#define WS_OFF   34048
#define SC_OFF   38400
#define C2_OFF   38464
#define X2P_OFF  38528
#define RM_OFF   38784
#define RS_OFF   38912
#define SA_OFF   39040
#define SMF_BYTES (39104 * 4)

__global__ void __launch_bounds__(256, 1)
fused_kernel(const float* __restrict__ X, const float* __restrict__ Cw,
             const float* __restrict__ scale, float* __restrict__ E) {
    extern __shared__ float sm[];
    unsigned int* smU = reinterpret_cast<unsigned int*>(sm);
    const int t = threadIdx.x, lane = t & 31, w = t >> 5;
    const int g = lane >> 2, tg = lane & 3;
    const int b = blockIdx.y;
    const int gn0 = blockIdx.x << 10;          // 1024 pixels per CTA

    // MMA1 warp tile: 16n x 32k   (warps: n-tile = w&3, k-half = w>>2)
    const int n0w1 = (w & 3) << 4, k0w1 = (w >> 2) << 5, kh = w >> 2;
    // MMA2 warp tile: 32k x 64d   (warps: k-half = w&1, d-tile = w>>1)
    const int k0w2 = (w & 1) << 5, d0w2 = (w >> 1) << 6;

    // ---- stage C (tf32) + scale; zero smem sumA ----
    #pragma unroll 4
    for (int i = 0; i < 64; ++i) {
        int idx = t + (i << 8);
        int k = idx >> 8, d = idx & 255;
        smU[CS_OFF + k * 260 + d] = f2tf32(Cw[idx]);
    }
    if (t < 64) { sm[SC_OFF + t] = scale[t]; sm[SA_OFF + t] = 0.0f; }
    __syncthreads();
    if (t < 64) {
        float s = 0.0f;
        #pragma unroll 8
        for (int d = 0; d < 256; ++d) {
            float c = __uint_as_float(smU[CS_OFF + t * 260 + d]);
            s += c * c;
        }
        sm[C2_OFF + t] = s;
    }
    __syncthreads();

    float scv[4][2], c2v[4][2];        // thread-invariant k metadata
    #pragma unroll
    for (int kt = 0; kt < 4; ++kt)
        #pragma unroll
        for (int j = 0; j < 2; ++j) {
            int k = k0w1 + (kt << 3) + (tg << 1) + j;
            scv[kt][j] = sm[SC_OFF + k];
            c2v[kt][j] = sm[C2_OFF + k];
        }

    float accE[2][8][4];
    #pragma unroll
    for (int m = 0; m < 2; ++m)
        #pragma unroll
        for (int dt = 0; dt < 8; ++dt)
            #pragma unroll
            for (int j = 0; j < 4; ++j) accE[m][dt][j] = 0.0f;
    float sk[4][2] = {{0.f,0.f},{0.f,0.f},{0.f,0.f},{0.f,0.f}};

    const float* Xg = X + (size_t)b * DD * NPIX + gn0;
    float* Eb = E + (size_t)b * KK * DD;

    for (int ch = 0; ch < 16; ++ch) {
        __syncthreads();                      // prev chunk's Xs/Ws/X2P readers done
        const int n0 = ch << 6;

        // ---- stage X chunk [256 d][64 n] (+ exact fp32 x2 partials) ----
        float x2p = 0.0f;
        #pragma unroll 8
        for (int i = 0; i < 64; ++i) {
            int idx = t + (i << 8);
            int d = idx >> 6, n = idx & 63;   // n == t&63 (invariant)
            float v = Xg[(size_t)d * NPIX + n0 + n];
            x2p += v * v;
            smU[XS_OFF + d * 68 + n] = f2tf32(v);
        }
        sm[X2P_OFF + t] = x2p;
        __syncthreads();

        // ---- MMA1: S[64n x 64k], K = 256 ----
        float acc1[4][4];
        #pragma unroll
        for (int kt = 0; kt < 4; ++kt)
            #pragma unroll
            for (int j = 0; j < 4; ++j) acc1[kt][j] = 0.0f;
        #pragma unroll 4
        for (int dd = 0; dd < 256; dd += 8) {
            unsigned int afr[4], bfr[4][2];
            #pragma unroll
            for (int i = 0; i < 4; ++i)
                afr[i] = smU[XS_OFF + (dd + tg + ((i >> 1) << 2)) * 68
                             + n0w1 + g + ((i & 1) << 3)];
            #pragma unroll
            for (int kt = 0; kt < 4; ++kt)
                #pragma unroll
                for (int j = 0; j < 2; ++j)
                    bfr[kt][j] = smU[CS_OFF + (k0w1 + (kt << 3) + g) * 260
                                     + dd + tg + (j << 2)];
            #pragma unroll
            for (int kt = 0; kt < 4; ++kt) mma_tf32(acc1[kt], afr, bfr[kt]);
        }

        // ---- softmax epilogue on fragments ----
        const int r0 = n0w1 + g, r1 = r0 + 8;
        float x2v0 = sm[X2P_OFF + r0] + sm[X2P_OFF + r0 + 64]
                   + sm[X2P_OFF + r0 + 128] + sm[X2P_OFF + r0 + 192];
        float x2v1 = sm[X2P_OFF + r1] + sm[X2P_OFF + r1 + 64]
                   + sm[X2P_OFF + r1 + 128] + sm[X2P_OFF + r1 + 192];
        float rm0 = -1e30f, rm1 = -1e30f;
        #pragma unroll
        for (int kt = 0; kt < 4; ++kt)
            #pragma unroll
            for (int j = 0; j < 4; ++j) {
                float x2 = (j & 2) ? x2v1 : x2v0;
                float l = scv[kt][j & 1] * (x2 - 2.0f * acc1[kt][j] + c2v[kt][j & 1]);
                acc1[kt][j] = l;
                if (j & 2) rm1 = fmaxf(rm1, l); else rm0 = fmaxf(rm0, l);
            }
        rm0 = fmaxf(rm0, __shfl_xor_sync(~0u, rm0, 1));
        rm0 = fmaxf(rm0, __shfl_xor_sync(~0u, rm0, 2));
        rm1 = fmaxf(rm1, __shfl_xor_sync(~0u, rm1, 1));
        rm1 = fmaxf(rm1, __shfl_xor_sync(~0u, rm1, 2));
        if (tg == 0) { sm[RM_OFF + (kh << 6) + r0] = rm0;
                       sm[RM_OFF + (kh << 6) + r1] = rm1; }
        __syncthreads();
        rm0 = fmaxf(rm0, sm[RM_OFF + ((1 - kh) << 6) + r0]);
        rm1 = fmaxf(rm1, sm[RM_OFF + ((1 - kh) << 6) + r1]);
        float rs0 = 0.0f, rs1 = 0.0f;
        #pragma unroll
        for (int kt = 0; kt < 4; ++kt)
            #pragma unroll
            for (int j = 0; j < 4; ++j) {
                float e = __expf(acc1[kt][j] - ((j & 2) ? rm1 : rm0));
                acc1[kt][j] = e;
                if (j & 2) rs1 += e; else rs0 += e;
            }
        rs0 += __shfl_xor_sync(~0u, rs0, 1);
        rs0 += __shfl_xor_sync(~0u, rs0, 2);
        rs1 += __shfl_xor_sync(~0u, rs1, 1);
        rs1 += __shfl_xor_sync(~0u, rs1, 2);
        if (tg == 0) { sm[RS_OFF + (kh << 6) + r0] = rs0;
                       sm[RS_OFF + (kh << 6) + r1] = rs1; }
        __syncthreads();
        const float inv0 = 1.0f / (rs0 + sm[RS_OFF + ((1 - kh) << 6) + r0]);
        const float inv1 = 1.0f / (rs1 + sm[RS_OFF + ((1 - kh) << 6) + r1]);
        const int kc = k0w1 + (tg << 1);
        #pragma unroll
        for (int kt = 0; kt < 4; ++kt) {
            float w0 = acc1[kt][0] * inv0, w1 = acc1[kt][1] * inv0;
            float w2 = acc1[kt][2] * inv1, w3 = acc1[kt][3] * inv1;
            sk[kt][0] += w0 + w2;
            sk[kt][1] += w1 + w3;
            uint2 p0 = make_uint2(f2tf32(w0), f2tf32(w1));
            uint2 p1 = make_uint2(f2tf32(w2), f2tf32(w3));
            *reinterpret_cast<uint2*>(&smU[WS_OFF + r0 * 68 + kc + (kt << 3)]) = p0;
            *reinterpret_cast<uint2*>(&smU[WS_OFF + r1 * 68 + kc + (kt << 3)]) = p1;
        }
        __syncthreads();                      // Ws ready for MMA2

        // ---- MMA2: accE += W^T (64k x 64n) * X (64n x 256d) ----
        #pragma unroll
        for (int ns = 0; ns < 64; ns += 8) {
            unsigned int afr2[2][4], bfr2[8][2];
            #pragma unroll
            for (int m = 0; m < 2; ++m)
                #pragma unroll
                for (int i = 0; i < 4; ++i)
                    afr2[m][i] = smU[WS_OFF + (ns + tg + ((i >> 1) << 2)) * 68
                                     + k0w2 + (m << 4) + g + ((i & 1) << 3)];
            #pragma unroll
            for (int dt = 0; dt < 8; ++dt)
                #pragma unroll
                for (int j = 0; j < 2; ++j)
                    bfr2[dt][j] = smU[XS_OFF + (d0w2 + (dt << 3) + g) * 68
                                      + ns + tg + (j << 2)];
            #pragma unroll
            for (int m = 0; m < 2; ++m)
                #pragma unroll
                for (int dt = 0; dt < 8; ++dt)
                    mma_tf32(accE[m][dt], afr2[m], bfr2[dt]);
        }
    }

    // ---- sumA: reduce over g via shfl butterfly, commit via smem ----
    #pragma unroll
    for (int kt = 0; kt < 4; ++kt)
        #pragma unroll
        for (int j = 0; j < 2; ++j) {
            float v = sk[kt][j];
            v += __shfl_xor_sync(~0u, v, 4);
            v += __shfl_xor_sync(~0u, v, 8);
            v += __shfl_xor_sync(~0u, v, 16);
            if (lane < 4)
                atomicAdd(&sm[SA_OFF + k0w1 + (kt << 3) + (tg << 1) + j], v);
        }
    __syncthreads();
    if (t < 64) atomicAdd(&g_sumA[(b << 6) + t], sm[SA_OFF + t]);

    // ---- commit register E tile (one atomic pass) ----
    #pragma unroll
    for (int m = 0; m < 2; ++m)
        #pragma unroll
        for (int dt = 0; dt < 8; ++dt)
            #pragma unroll
            for (int j = 0; j < 4; ++j) {
                int k = k0w2 + (m << 4) + g + ((j >> 1) << 3);
                int d = d0w2 + (dt << 3) + (tg << 1) + (j & 1);
                atomicAdd(&Eb[(size_t)k * DD + d], accE[m][dt][j]);
            }
}

// ---------------------------------------------------------------------------
// Finalize: E[b,k,d] -= sumA[b,k] * C[k,d]   (exact fp32)
// ---------------------------------------------------------------------------
__global__ void finalize_kernel(const float* __restrict__ Cw, float* __restrict__ E) {
    int idx = blockIdx.x * 256 + threadIdx.x;
    if (idx >= BD * KK * DD) return;
    int kd = idx & (KK * DD - 1);
    int b  = idx >> 14;
    E[idx] -= g_sumA[(b << 6) + (kd >> 8)] * Cw[kd];
}

// ---------------------------------------------------------------------------
// Launch. Inputs: X [16,256,96,96] f32, codewords [64,256] f32, scale [64] f32.
// Output E [16,64,256] f32.
// ---------------------------------------------------------------------------
extern "C" void kernel_launch(void* const* d_in, const int* in_sizes, int n_in,
                              void* d_out, int out_size) {
    const float* X     = (const float*)d_in[0];
    const float* Cw    = (const float*)d_in[1];
    const float* scale = (const float*)d_in[2];
    float* E = (float*)d_out;

    cudaFuncSetAttribute(fused_kernel,
                         cudaFuncAttributeMaxDynamicSharedMemorySize, SMF_BYTES);

    zero_kernel<<<1024, 256>>>(E);
    fused_kernel<<<dim3(NPIX / 1024, BD), 256, SMF_BYTES>>>(X, Cw, scale, E);
    finalize_kernel<<<1024, 256>>>(Cw, E);
}

// round 11
// speedup vs baseline: 4.7902x; 1.4658x over previous
#include <cuda_runtime.h>
#include <math.h>

// Problem constants: B=16, D=256, K=64, H=W=96 -> N=9216
#define BD   16
#define DD   256
#define KK   64
#define NPIX 9216

__device__ float g_sumA[BD * KK];

// ---- tf32 / mma / ldmatrix helpers ----------------------------------------
__device__ __forceinline__ unsigned int f2tf32(float x) {
    unsigned int u;
    asm("cvt.rna.tf32.f32 %0, %1;" : "=r"(u) : "f"(x));
    return u;
}
__device__ __forceinline__ void mma_tf32(float* c, const unsigned int* a,
                                         const unsigned int* b) {
    asm("mma.sync.aligned.m16n8k8.row.col.f32.tf32.tf32.f32 "
        "{%0,%1,%2,%3}, {%4,%5,%6,%7}, {%8,%9}, {%0,%1,%2,%3};"
        : "+f"(c[0]), "+f"(c[1]), "+f"(c[2]), "+f"(c[3])
        : "r"(a[0]), "r"(a[1]), "r"(a[2]), "r"(a[3]), "r"(b[0]), "r"(b[1]));
}
#define LDSM4(r0, r1, r2, r3, addr)                                          \
    asm volatile("ldmatrix.sync.aligned.m8n8.x4.shared.b16 {%0,%1,%2,%3}, [%4];" \
                 : "=r"(r0), "=r"(r1), "=r"(r2), "=r"(r3) : "r"(addr))

// X-tile swizzle: word offset of (d, n) inside the [256][64] tile.
// Conflict-free for BOTH row-by-tg scalar A-loads and row-by-g ldmatrix B-rows;
// keeps 4-word (16B) n-groups contiguous (ldmatrix-legal).
__device__ __forceinline__ int XW(int d, int n) {
    return (d << 6) | (n ^ (((d & 7) << 3) | (d & 4)));
}

// ---------------------------------------------------------------------------
// Kernel 0: zero output + g_sumA
// ---------------------------------------------------------------------------
__global__ void zero_kernel(float* __restrict__ E) {
    int i = blockIdx.x * 256 + threadIdx.x;
    if (i < BD * KK * DD) E[i] = 0.0f;
    if (i < BD * KK)      g_sumA[i] = 0.0f;
}

// ---------------------------------------------------------------------------
// Fused kernel. SMEM word offsets:
//   CS 0     : C tf32 [64][260]           (16640)
//   XS 16640 : X tf32 [256][64] swizzled  (16384)
//   WS 33024 : W tf32 [64 k][68 n]        (4352)
//   SC 37376 [64], C2 37440 [64], X2P 37504 [8][64]=512,
//   RMS 38016 [2][64] float2 = 256, SA 38272 [64]
// total 38336 words = 153344 B -> occupancy 1
// ---------------------------------------------------------------------------
#define CS_OFF   0
#define XS_OFF   16640
#define WS_OFF   33024
#define SC_OFF   37376
#define C2_OFF   37440
#define X2P_OFF  37504
#define RMS_OFF  38016
#define SA_OFF   38272
#define SMF_BYTES (38336 * 4)

__global__ void __launch_bounds__(256, 1)
fused_kernel(const float* __restrict__ X, const float* __restrict__ Cw,
             const float* __restrict__ scale, float* __restrict__ E) {
    extern __shared__ float sm[];
    unsigned int* smU = reinterpret_cast<unsigned int*>(sm);
    unsigned int smb;
    asm("{ .reg .u64 t; cvta.to.shared.u64 t, %1; cvt.u32.u64 %0, t; }"
        : "=r"(smb) : "l"(sm));

    const int t = threadIdx.x, lane = t & 31, wp = t >> 5;
    const int g = lane >> 2, tg = lane & 3;
    const int b = blockIdx.y;
    const int gn0 = blockIdx.x << 10;

    // MMA1 warp tile: 16n x 32k ; MMA2 warp tile: 32k x 64d
    const int n0w1 = (wp & 3) << 4, k0w1 = (wp >> 2) << 5, kh = wp >> 2;
    const int k0w2 = (wp & 1) << 5, d0w2 = (wp >> 1) << 6;

    // ---- stage C (tf32) + scale; zero smem sumA ----
    #pragma unroll 4
    for (int i = 0; i < 64; ++i) {
        int idx = t + (i << 8);
        int k = idx >> 8, d = idx & 255;
        smU[CS_OFF + k * 260 + d] = f2tf32(Cw[idx]);
    }
    if (t < 64) { sm[SC_OFF + t] = scale[t]; sm[SA_OFF + t] = 0.0f; }
    __syncthreads();
    if (t < 64) {
        float s = 0.0f;
        #pragma unroll 8
        for (int d = 0; d < 256; ++d) {
            float c = __uint_as_float(smU[CS_OFF + t * 260 + d]);
            s += c * c;
        }
        sm[C2_OFF + t] = s;
    }
    __syncthreads();

    float scv[4][2], c2v[4][2];
    #pragma unroll
    for (int kt = 0; kt < 4; ++kt)
        #pragma unroll
        for (int j = 0; j < 2; ++j) {
            int k = k0w1 + (kt << 3) + (tg << 1) + j;
            scv[kt][j] = sm[SC_OFF + k];
            c2v[kt][j] = sm[C2_OFF + k];
        }

    // ---- per-thread fragment address bases ----
    // MMA1-A (scalar, swizzled XS): i2 = d-offset(+4), i1 = n-offset(+8)
    int nxA[2][2], dA[2];
    #pragma unroll
    for (int i2 = 0; i2 < 2; ++i2) {
        dA[i2] = tg + (i2 << 2);
        int perm = ((tg + (i2 << 2)) << 3) | (i2 << 2);
        #pragma unroll
        for (int i1 = 0; i1 < 2; ++i1)
            nxA[i2][i1] = (n0w1 + g + (i1 << 3)) ^ perm;
    }
    // MMA1-B ldmatrix base (C): lane -> kt-half=(lane>>4)&1, j=(lane>>3)&1, row=lane&7
    const unsigned int b1_base = smb +
        4u * (CS_OFF + (k0w1 + (((lane >> 4) & 1) << 3) + (lane & 7)) * 260
              + (((lane >> 3) & 1) << 2));
    // MMA2-A ldmatrix base (W [k][68]): i1=(lane>>3)&1 (k+8), i2=(lane>>4)&1 (n+4)
    const unsigned int a2_base = smb +
        4u * (WS_OFF + (k0w2 + (((lane >> 3) & 1) << 3) + (lane & 7)) * 68
              + (((lane >> 4) & 1) << 2));
    // MMA2-B ldmatrix (swizzled XS): dt-half=(lane>>4)&1, j=(lane>>3)&1, row=lane&7
    const int rB = lane & 7;
    const int permB = (rB << 3) | (rB & 4);
    const int jB4 = ((lane >> 3) & 1) << 2;
    unsigned int b2_base[4];
    #pragma unroll
    for (int q = 0; q < 4; ++q)
        b2_base[q] = smb + 4u * (XS_OFF +
            ((d0w2 + (((q << 1) + ((lane >> 4) & 1)) << 3) + rB) << 6));

    float accE[2][8][4];
    #pragma unroll
    for (int m = 0; m < 2; ++m)
        #pragma unroll
        for (int dt = 0; dt < 8; ++dt)
            #pragma unroll
            for (int j = 0; j < 4; ++j) accE[m][dt][j] = 0.0f;
    float sk[4][2] = {{0.f,0.f},{0.f,0.f},{0.f,0.f},{0.f,0.f}};

    const float* Xg = X + (size_t)b * DD * NPIX + gn0;
    float* Eb = E + (size_t)b * KK * DD;

    for (int ch = 0; ch < 16; ++ch) {
        __syncthreads();
        const int n0 = ch << 6;

        // ---- stage X chunk (float2 loads; exact fp32 x2 partials) ----
        {
            const int nl = lane << 1;
            float p0 = 0.0f, p1 = 0.0f;
            #pragma unroll 8
            for (int i = 0; i < 32; ++i) {
                int d = wp + (i << 3);
                float2 xv = *reinterpret_cast<const float2*>(
                    Xg + (size_t)d * NPIX + n0 + nl);
                p0 += xv.x * xv.x;
                p1 += xv.y * xv.y;
                uint2 pv = make_uint2(f2tf32(xv.x), f2tf32(xv.y));
                *reinterpret_cast<uint2*>(&smU[XS_OFF + XW(d, nl)]) = pv;
            }
            *reinterpret_cast<float2*>(&sm[X2P_OFF + (wp << 6) + nl]) =
                make_float2(p0, p1);
        }
        __syncthreads();

        // ---- MMA1: S[64n x 64k], K = 256 ----
        float acc1[4][4];
        #pragma unroll
        for (int kt = 0; kt < 4; ++kt)
            #pragma unroll
            for (int j = 0; j < 4; ++j) acc1[kt][j] = 0.0f;
        #pragma unroll
        for (int dd = 0; dd < 256; dd += 8) {
            unsigned int afr[4], bfr[4][2];
            afr[0] = smU[XS_OFF + ((dd + dA[0]) << 6) + nxA[0][0]];
            afr[1] = smU[XS_OFF + ((dd + dA[0]) << 6) + nxA[0][1]];
            afr[2] = smU[XS_OFF + ((dd + dA[1]) << 6) + nxA[1][0]];
            afr[3] = smU[XS_OFF + ((dd + dA[1]) << 6) + nxA[1][1]];
            LDSM4(bfr[0][0], bfr[0][1], bfr[1][0], bfr[1][1],
                  b1_base + 4u * dd);
            LDSM4(bfr[2][0], bfr[2][1], bfr[3][0], bfr[3][1],
                  b1_base + 4u * dd + 4u * 16 * 260);
            #pragma unroll
            for (int kt = 0; kt < 4; ++kt) mma_tf32(acc1[kt], afr, bfr[kt]);
        }

        // ---- logits + online softmax (single exchange) ----
        const int r0 = n0w1 + g, r1 = r0 + 8;
        float x2v0 = 0.0f, x2v1 = 0.0f;
        #pragma unroll
        for (int q = 0; q < 8; ++q) {
            x2v0 += sm[X2P_OFF + (q << 6) + r0];
            x2v1 += sm[X2P_OFF + (q << 6) + r1];
        }
        float rm0 = -1e30f, rm1 = -1e30f;
        #pragma unroll
        for (int kt = 0; kt < 4; ++kt)
            #pragma unroll
            for (int j = 0; j < 4; ++j) {
                float x2 = (j & 2) ? x2v1 : x2v0;
                float l = scv[kt][j & 1] * (x2 - 2.0f * acc1[kt][j] + c2v[kt][j & 1]);
                acc1[kt][j] = l;
                if (j & 2) rm1 = fmaxf(rm1, l); else rm0 = fmaxf(rm0, l);
            }
        rm0 = fmaxf(rm0, __shfl_xor_sync(~0u, rm0, 1));
        rm0 = fmaxf(rm0, __shfl_xor_sync(~0u, rm0, 2));
        rm1 = fmaxf(rm1, __shfl_xor_sync(~0u, rm1, 1));
        rm1 = fmaxf(rm1, __shfl_xor_sync(~0u, rm1, 2));
        float rs0 = 0.0f, rs1 = 0.0f;
        #pragma unroll
        for (int kt = 0; kt < 4; ++kt)
            #pragma unroll
            for (int j = 0; j < 4; ++j) {
                float e = __expf(acc1[kt][j] - ((j & 2) ? rm1 : rm0));
                acc1[kt][j] = e;
                if (j & 2) rs1 += e; else rs0 += e;
            }
        rs0 += __shfl_xor_sync(~0u, rs0, 1);
        rs0 += __shfl_xor_sync(~0u, rs0, 2);
        rs1 += __shfl_xor_sync(~0u, rs1, 1);
        rs1 += __shfl_xor_sync(~0u, rs1, 2);
        if (tg == 0) {
            *reinterpret_cast<float2*>(&sm[RMS_OFF + ((kh << 6) + r0) * 2]) =
                make_float2(rm0, rs0);
            *reinterpret_cast<float2*>(&sm[RMS_OFF + ((kh << 6) + r1) * 2]) =
                make_float2(rm1, rs1);
        }
        __syncthreads();
        float2 o0 = *reinterpret_cast<float2*>(
            &sm[RMS_OFF + (((1 - kh) << 6) + r0) * 2]);
        float2 o1 = *reinterpret_cast<float2*>(
            &sm[RMS_OFF + (((1 - kh) << 6) + r1) * 2]);
        // merged softmax: factor = exp(rm_local - M) / total
        float M0 = fmaxf(rm0, o0.x), M1 = fmaxf(rm1, o1.x);
        float tot0 = rs0 * __expf(rm0 - M0) + o0.y * __expf(o0.x - M0);
        float tot1 = rs1 * __expf(rm1 - M1) + o1.y * __expf(o1.x - M1);
        float f0 = __expf(rm0 - M0) / tot0;
        float f1 = __expf(rm1 - M1) / tot1;

        // ---- W -> smem as [k][68] (ldmatrix-friendly for MMA2-A) ----
        const int kc = k0w1 + (tg << 1);
        #pragma unroll
        for (int kt = 0; kt < 4; ++kt) {
            float w0 = acc1[kt][0] * f0, w1 = acc1[kt][1] * f0;
            float w2 = acc1[kt][2] * f1, w3 = acc1[kt][3] * f1;
            sk[kt][0] += w0 + w2;
            sk[kt][1] += w1 + w3;
            int kr = kc + (kt << 3);
            smU[WS_OFF + kr * 68 + r0]       = f2tf32(w0);
            smU[WS_OFF + (kr + 1) * 68 + r0] = f2tf32(w1);
            smU[WS_OFF + kr * 68 + r1]       = f2tf32(w2);
            smU[WS_OFF + (kr + 1) * 68 + r1] = f2tf32(w3);
        }
        __syncthreads();

        // ---- MMA2: accE += W^T (64k x 64n) * X (64n x 256d) ----
        #pragma unroll
        for (int ns = 0; ns < 64; ns += 8) {
            unsigned int a2[2][4], b2[8][2];
            LDSM4(a2[0][0], a2[0][1], a2[0][2], a2[0][3], a2_base + 4u * ns);
            LDSM4(a2[1][0], a2[1][1], a2[1][2], a2[1][3],
                  a2_base + 4u * ns + 4u * 16 * 68);
            const unsigned int nsx = 4u * (unsigned)((ns | jB4) ^ permB);
            #pragma unroll
            for (int q = 0; q < 4; ++q)
                LDSM4(b2[2 * q][0], b2[2 * q][1], b2[2 * q + 1][0],
                      b2[2 * q + 1][1], b2_base[q] + nsx);
            #pragma unroll
            for (int m = 0; m < 2; ++m)
                #pragma unroll
                for (int dt = 0; dt < 8; ++dt)
                    mma_tf32(accE[m][dt], a2[m], b2[dt]);
        }
    }

    // ---- sumA: butterfly over g, commit via smem + one global atomic ----
    #pragma unroll
    for (int kt = 0; kt < 4; ++kt)
        #pragma unroll
        for (int j = 0; j < 2; ++j) {
            float v = sk[kt][j];
            v += __shfl_xor_sync(~0u, v, 4);
            v += __shfl_xor_sync(~0u, v, 8);
            v += __shfl_xor_sync(~0u, v, 16);
            if (lane < 4)
                atomicAdd(&sm[SA_OFF + k0w1 + (kt << 3) + (tg << 1) + j], v);
        }
    __syncthreads();
    if (t < 64) atomicAdd(&g_sumA[(b << 6) + t], sm[SA_OFF + t]);

    // ---- commit register E tile (one atomic pass) ----
    #pragma unroll
    for (int m = 0; m < 2; ++m)
        #pragma unroll
        for (int dt = 0; dt < 8; ++dt)
            #pragma unroll
            for (int j = 0; j < 4; ++j) {
                int k = k0w2 + (m << 4) + g + ((j >> 1) << 3);
                int d = d0w2 + (dt << 3) + (tg << 1) + (j & 1);
                atomicAdd(&Eb[(size_t)k * DD + d], accE[m][dt][j]);
            }
}

// ---------------------------------------------------------------------------
// Finalize: E[b,k,d] -= sumA[b,k] * C[k,d]   (exact fp32)
// ---------------------------------------------------------------------------
__global__ void finalize_kernel(const float* __restrict__ Cw, float* __restrict__ E) {
    int idx = blockIdx.x * 256 + threadIdx.x;
    if (idx >= BD * KK * DD) return;
    int kd = idx & (KK * DD - 1);
    int b  = idx >> 14;
    E[idx] -= g_sumA[(b << 6) + (kd >> 8)] * Cw[kd];
}

// ---------------------------------------------------------------------------
extern "C" void kernel_launch(void* const* d_in, const int* in_sizes, int n_in,
                              void* d_out, int out_size) {
    const float* X     = (const float*)d_in[0];
    const float* Cw    = (const float*)d_in[1];
    const float* scale = (const float*)d_in[2];
    float* E = (float*)d_out;

    cudaFuncSetAttribute(fused_kernel,
                         cudaFuncAttributeMaxDynamicSharedMemorySize, SMF_BYTES);

    zero_kernel<<<1024, 256>>>(E);
    fused_kernel<<<dim3(NPIX / 1024, BD), 256, SMF_BYTES>>>(X, Cw, scale, E);
    finalize_kernel<<<1024, 256>>>(Cw, E);
}

// round 12
// speedup vs baseline: 6.9684x; 1.4547x over previous
#include <cuda_runtime.h>
#include <math.h>

// Problem constants: B=16, D=256, K=64, H=W=96 -> N=9216
#define BD   16
#define DD   256
#define KK   64
#define NPIX 9216

__device__ float g_sumA[BD * KK];

// ---- tf32 / mma / ldmatrix / cp.async helpers ------------------------------
__device__ __forceinline__ unsigned int f2tf32(float x) {
    unsigned int u;
    asm("cvt.rna.tf32.f32 %0, %1;" : "=r"(u) : "f"(x));
    return u;
}
__device__ __forceinline__ void mma_tf32(float* c, const unsigned int* a,
                                         const unsigned int* b) {
    asm("mma.sync.aligned.m16n8k8.row.col.f32.tf32.tf32.f32 "
        "{%0,%1,%2,%3}, {%4,%5,%6,%7}, {%8,%9}, {%0,%1,%2,%3};"
        : "+f"(c[0]), "+f"(c[1]), "+f"(c[2]), "+f"(c[3])
        : "r"(a[0]), "r"(a[1]), "r"(a[2]), "r"(a[3]), "r"(b[0]), "r"(b[1]));
}
#define LDSM4(r0, r1, r2, r3, addr)                                          \
    asm volatile("ldmatrix.sync.aligned.m8n8.x4.shared.b16 {%0,%1,%2,%3}, [%4];" \
                 : "=r"(r0), "=r"(r1), "=r"(r2), "=r"(r3) : "r"(addr))
__device__ __forceinline__ void cp16(unsigned int saddr, const void* g) {
    asm volatile("cp.async.cg.shared.global [%0], [%1], 16;"
                 :: "r"(saddr), "l"(g));
}
#define CP_COMMIT() asm volatile("cp.async.commit_group;" ::: "memory")
#define CP_WAIT0()  asm volatile("cp.async.wait_group 0;"  ::: "memory")

// X-tile swizzle: word offset of (d, n) inside a [256][64] buffer.
// XORs only n bits [2:5] -> 16B groups stay contiguous (cp.async/ldmatrix-legal);
// conflict-free for row-by-tg scalar A-loads and row-by-g ldmatrix B-rows.
__device__ __forceinline__ int XW(int d, int n) {
    return (d << 6) | (n ^ (((d & 7) << 3) | (d & 4)));
}

// ---------------------------------------------------------------------------
// Kernel 0: zero output + g_sumA
// ---------------------------------------------------------------------------
__global__ void zero_kernel(float* __restrict__ E) {
    int i = blockIdx.x * 256 + threadIdx.x;
    if (i < BD * KK * DD) E[i] = 0.0f;
    if (i < BD * KK)      g_sumA[i] = 0.0f;
}

// ---------------------------------------------------------------------------
// Fused kernel. SMEM word offsets:
//   CS  0     : C tf32 [64][260]              (16640)
//   XS0 16640 : X raw fp32 [256][64] swz      (16384)  } double
//   XS1 33024 : X raw fp32 [256][64] swz      (16384)  } buffer
//   WS  49408 : W tf32 [64 k][68 n]           (4352)
//   SC 53760 [64], C2 53824 [64], RMS 53888 [2][64]x2 = 256, SA 54144 [64]
// total 54208 words = 216832 B -> occupancy 1
// ---------------------------------------------------------------------------
#define CS_OFF   0
#define XS0_OFF  16640
#define XSBUF    16384
#define WS_OFF   49408
#define SC_OFF   53760
#define C2_OFF   53824
#define RMS_OFF  53888
#define SA_OFF   54144
#define SMF_BYTES (54208 * 4)

__global__ void __launch_bounds__(256, 1)
fused_kernel(const float* __restrict__ X, const float* __restrict__ Cw,
             const float* __restrict__ scale, float* __restrict__ E) {
    extern __shared__ float sm[];
    unsigned int* smU = reinterpret_cast<unsigned int*>(sm);
    unsigned int smb;
    asm("{ .reg .u64 t; cvta.to.shared.u64 t, %1; cvt.u32.u64 %0, t; }"
        : "=r"(smb) : "l"(sm));

    const int t = threadIdx.x, lane = t & 31, wp = t >> 5;
    const int g = lane >> 2, tg = lane & 3;
    const int b = blockIdx.y;
    const int gn0 = blockIdx.x << 10;

    const int n0w1 = (wp & 3) << 4, k0w1 = (wp >> 2) << 5, kh = wp >> 2;
    const int k0w2 = (wp & 1) << 5, d0w2 = (wp >> 1) << 6;

    const float* Xg = X + (size_t)b * DD * NPIX + gn0;
    float* Eb = E + (size_t)b * KK * DD;

    // staging geometry: thread t owns n-group gi4 = (t&15)*4, rows d = t>>4 + 16i
    const int gi4 = (t & 15) << 2;
    const int db0 = t >> 4;

    // ---- prologue: kick off chunk 0 copy immediately ----
    {
        #pragma unroll
        for (int i = 0; i < 16; ++i) {
            int d = db0 + (i << 4);
            cp16(smb + 4u * (XS0_OFF + ((d << 6) |
                      (gi4 ^ (((d & 7) << 3) | (d & 4))))),
                 Xg + (size_t)d * NPIX + gi4);
        }
        CP_COMMIT();
    }

    // ---- stage C (tf32 RNA) + scale; zero smem sumA (overlaps G0) ----
    #pragma unroll 4
    for (int i = 0; i < 64; ++i) {
        int idx = t + (i << 8);
        int k = idx >> 8, d = idx & 255;
        smU[CS_OFF + k * 260 + d] = f2tf32(Cw[idx]);
    }
    if (t < 64) { sm[SC_OFF + t] = scale[t]; sm[SA_OFF + t] = 0.0f; }
    __syncthreads();
    if (t < 64) {
        float s = 0.0f;
        #pragma unroll 8
        for (int d = 0; d < 256; ++d) {
            float c = __uint_as_float(smU[CS_OFF + t * 260 + d]);
            s += c * c;
        }
        sm[C2_OFF + t] = s;
    }

    float scv[4][2], c2v[4][2];
    __syncthreads();
    #pragma unroll
    for (int kt = 0; kt < 4; ++kt)
        #pragma unroll
        for (int j = 0; j < 2; ++j) {
            int k = k0w1 + (kt << 3) + (tg << 1) + j;
            scv[kt][j] = sm[SC_OFF + k];
            c2v[kt][j] = sm[C2_OFF + k];
        }

    // ---- fragment address precomputes ----
    int nxA[2][2];
    const int dA0 = tg, dA1 = tg + 4;
    #pragma unroll
    for (int i2 = 0; i2 < 2; ++i2) {
        int d = tg + (i2 << 2);
        int perm = ((d & 7) << 3) | (d & 4);
        #pragma unroll
        for (int i1 = 0; i1 < 2; ++i1)
            nxA[i2][i1] = (n0w1 + g + (i1 << 3)) ^ perm;
    }
    const unsigned int b1_base = smb +
        4u * (CS_OFF + (k0w1 + (((lane >> 4) & 1) << 3) + (lane & 7)) * 260
              + (((lane >> 3) & 1) << 2));
    const unsigned int a2_base = smb +
        4u * (WS_OFF + (k0w2 + (((lane >> 3) & 1) << 3) + (lane & 7)) * 68
              + (((lane >> 4) & 1) << 2));
    const int rB = lane & 7;
    const int permB = (rB << 3) | (rB & 4);
    const int jB4 = ((lane >> 3) & 1) << 2;
    unsigned int b2_row[4];
    #pragma unroll
    for (int q = 0; q < 4; ++q)
        b2_row[q] = 4u * (unsigned)(((d0w2 + (((q << 1) + ((lane >> 4) & 1)) << 3)
                                      + rB) << 6));

    float accE[2][8][4];
    #pragma unroll
    for (int m = 0; m < 2; ++m)
        #pragma unroll
        for (int dt = 0; dt < 8; ++dt)
            #pragma unroll
            for (int j = 0; j < 4; ++j) accE[m][dt][j] = 0.0f;
    float sk[4][2] = {{0.f,0.f},{0.f,0.f},{0.f,0.f},{0.f,0.f}};

    for (int ch = 0; ch < 16; ++ch) {
        const int cur = ch & 1;
        const int xsO = XS0_OFF + (cur ? XSBUF : 0);
        const unsigned int xsB = smb + 4u * xsO;

        CP_WAIT0();                 // this thread's chunk-ch copies done
        __syncthreads();            // all threads' copies visible; prev readers done

        // ---- issue chunk ch+1 into the other buffer (hides under MMAs) ----
        if (ch < 15) {
            const int n1 = (ch + 1) << 6;
            const int oO = XS0_OFF + (cur ? 0 : XSBUF);
            #pragma unroll
            for (int i = 0; i < 16; ++i) {
                int d = db0 + (i << 4);
                cp16(smb + 4u * (oO + ((d << 6) |
                          (gi4 ^ (((d & 7) << 3) | (d & 4))))),
                     Xg + (size_t)d * NPIX + n1 + gi4);
            }
            CP_COMMIT();
        }

        // ---- MMA1: S[64n x 64k], K = 256 ; x2 from raw fragments ----
        float acc1[4][4];
        #pragma unroll
        for (int kt = 0; kt < 4; ++kt)
            #pragma unroll
            for (int j = 0; j < 4; ++j) acc1[kt][j] = 0.0f;
        float x2p0 = 0.0f, x2p1 = 0.0f;
        #pragma unroll
        for (int dd = 0; dd < 256; dd += 8) {
            float a0 = __uint_as_float(smU[xsO + ((dd + dA0) << 6) + nxA[0][0]]);
            float a1 = __uint_as_float(smU[xsO + ((dd + dA0) << 6) + nxA[0][1]]);
            float a2 = __uint_as_float(smU[xsO + ((dd + dA1) << 6) + nxA[1][0]]);
            float a3 = __uint_as_float(smU[xsO + ((dd + dA1) << 6) + nxA[1][1]]);
            x2p0 += a0 * a0 + a2 * a2;
            x2p1 += a1 * a1 + a3 * a3;
            unsigned int afr[4], bfr[4][2];
            afr[0] = f2tf32(a0); afr[1] = f2tf32(a1);
            afr[2] = f2tf32(a2); afr[3] = f2tf32(a3);
            LDSM4(bfr[0][0], bfr[0][1], bfr[1][0], bfr[1][1], b1_base + 4u * dd);
            LDSM4(bfr[2][0], bfr[2][1], bfr[3][0], bfr[3][1],
                  b1_base + 4u * dd + 4u * 16 * 260);
            #pragma unroll
            for (int kt = 0; kt < 4; ++kt) mma_tf32(acc1[kt], afr, bfr[kt]);
        }
        // exact x2: reduce over tg (lanes ^1, ^2 share g => same n rows)
        x2p0 += __shfl_xor_sync(~0u, x2p0, 1);
        x2p0 += __shfl_xor_sync(~0u, x2p0, 2);
        x2p1 += __shfl_xor_sync(~0u, x2p1, 1);
        x2p1 += __shfl_xor_sync(~0u, x2p1, 2);

        // ---- logits + online softmax (single cross-half exchange) ----
        const int r0 = n0w1 + g, r1 = r0 + 8;
        float rm0 = -1e30f, rm1 = -1e30f;
        #pragma unroll
        for (int kt = 0; kt < 4; ++kt)
            #pragma unroll
            for (int j = 0; j < 4; ++j) {
                float x2 = (j & 2) ? x2p1 : x2p0;
                float l = scv[kt][j & 1] * (x2 - 2.0f * acc1[kt][j] + c2v[kt][j & 1]);
                acc1[kt][j] = l;
                if (j & 2) rm1 = fmaxf(rm1, l); else rm0 = fmaxf(rm0, l);
            }
        rm0 = fmaxf(rm0, __shfl_xor_sync(~0u, rm0, 1));
        rm0 = fmaxf(rm0, __shfl_xor_sync(~0u, rm0, 2));
        rm1 = fmaxf(rm1, __shfl_xor_sync(~0u, rm1, 1));
        rm1 = fmaxf(rm1, __shfl_xor_sync(~0u, rm1, 2));
        float rs0 = 0.0f, rs1 = 0.0f;
        #pragma unroll
        for (int kt = 0; kt < 4; ++kt)
            #pragma unroll
            for (int j = 0; j < 4; ++j) {
                float e = __expf(acc1[kt][j] - ((j & 2) ? rm1 : rm0));
                acc1[kt][j] = e;
                if (j & 2) rs1 += e; else rs0 += e;
            }
        rs0 += __shfl_xor_sync(~0u, rs0, 1);
        rs0 += __shfl_xor_sync(~0u, rs0, 2);
        rs1 += __shfl_xor_sync(~0u, rs1, 1);
        rs1 += __shfl_xor_sync(~0u, rs1, 2);
        if (tg == 0) {
            *reinterpret_cast<float2*>(&sm[RMS_OFF + ((kh << 6) + r0) * 2]) =
                make_float2(rm0, rs0);
            *reinterpret_cast<float2*>(&sm[RMS_OFF + ((kh << 6) + r1) * 2]) =
                make_float2(rm1, rs1);
        }
        __syncthreads();
        float2 o0 = *reinterpret_cast<float2*>(
            &sm[RMS_OFF + (((1 - kh) << 6) + r0) * 2]);
        float2 o1 = *reinterpret_cast<float2*>(
            &sm[RMS_OFF + (((1 - kh) << 6) + r1) * 2]);
        float M0 = fmaxf(rm0, o0.x), M1 = fmaxf(rm1, o1.x);
        float tot0 = rs0 * __expf(rm0 - M0) + o0.y * __expf(o0.x - M0);
        float tot1 = rs1 * __expf(rm1 - M1) + o1.y * __expf(o1.x - M1);
        float f0 = __expf(rm0 - M0) / tot0;
        float f1 = __expf(rm1 - M1) / tot1;

        // ---- W -> smem [k][68] (tf32 RNA) ----
        const int kc = k0w1 + (tg << 1);
        #pragma unroll
        for (int kt = 0; kt < 4; ++kt) {
            float w0 = acc1[kt][0] * f0, w1 = acc1[kt][1] * f0;
            float w2 = acc1[kt][2] * f1, w3 = acc1[kt][3] * f1;
            sk[kt][0] += w0 + w2;
            sk[kt][1] += w1 + w3;
            int kr = kc + (kt << 3);
            smU[WS_OFF + kr * 68 + r0]       = f2tf32(w0);
            smU[WS_OFF + (kr + 1) * 68 + r0] = f2tf32(w1);
            smU[WS_OFF + kr * 68 + r1]       = f2tf32(w2);
            smU[WS_OFF + (kr + 1) * 68 + r1] = f2tf32(w3);
        }
        __syncthreads();

        // ---- MMA2: accE += W^T (64k x 64n) * X (64n x 256d) ----
        #pragma unroll
        for (int ns = 0; ns < 64; ns += 8) {
            unsigned int a2[2][4], b2[8][2];
            LDSM4(a2[0][0], a2[0][1], a2[0][2], a2[0][3], a2_base + 4u * ns);
            LDSM4(a2[1][0], a2[1][1], a2[1][2], a2[1][3],
                  a2_base + 4u * ns + 4u * 16 * 68);
            const unsigned int nsx = 4u * (unsigned)((ns | jB4) ^ permB);
            #pragma unroll
            for (int q = 0; q < 4; ++q)
                LDSM4(b2[2 * q][0], b2[2 * q][1], b2[2 * q + 1][0],
                      b2[2 * q + 1][1], xsB + b2_row[q] + nsx);
            #pragma unroll
            for (int dt = 0; dt < 8; ++dt) {
                b2[dt][0] = f2tf32(__uint_as_float(b2[dt][0]));
                b2[dt][1] = f2tf32(__uint_as_float(b2[dt][1]));
            }
            #pragma unroll
            for (int m = 0; m < 2; ++m)
                #pragma unroll
                for (int dt = 0; dt < 8; ++dt)
                    mma_tf32(accE[m][dt], a2[m], b2[dt]);
        }
    }

    // ---- sumA: butterfly over g, commit via smem + one global atomic ----
    #pragma unroll
    for (int kt = 0; kt < 4; ++kt)
        #pragma unroll
        for (int j = 0; j < 2; ++j) {
            float v = sk[kt][j];
            v += __shfl_xor_sync(~0u, v, 4);
            v += __shfl_xor_sync(~0u, v, 8);
            v += __shfl_xor_sync(~0u, v, 16);
            if (lane < 4)
                atomicAdd(&sm[SA_OFF + k0w1 + (kt << 3) + (tg << 1) + j], v);
        }
    __syncthreads();
    if (t < 64) atomicAdd(&g_sumA[(b << 6) + t], sm[SA_OFF + t]);

    // ---- commit register E tile (one atomic pass) ----
    #pragma unroll
    for (int m = 0; m < 2; ++m)
        #pragma unroll
        for (int dt = 0; dt < 8; ++dt)
            #pragma unroll
            for (int j = 0; j < 4; ++j) {
                int k = k0w2 + (m << 4) + g + ((j >> 1) << 3);
                int d = d0w2 + (dt << 3) + (tg << 1) + (j & 1);
                atomicAdd(&Eb[(size_t)k * DD + d], accE[m][dt][j]);
            }
}

// ---------------------------------------------------------------------------
// Finalize: E[b,k,d] -= sumA[b,k] * C[k,d]   (exact fp32)
// ---------------------------------------------------------------------------
__global__ void finalize_kernel(const float* __restrict__ Cw, float* __restrict__ E) {
    int idx = blockIdx.x * 256 + threadIdx.x;
    if (idx >= BD * KK * DD) return;
    int kd = idx & (KK * DD - 1);
    int b  = idx >> 14;
    E[idx] -= g_sumA[(b << 6) + (kd >> 8)] * Cw[kd];
}

// ---------------------------------------------------------------------------
extern "C" void kernel_launch(void* const* d_in, const int* in_sizes, int n_in,
                              void* d_out, int out_size) {
    const float* X     = (const float*)d_in[0];
    const float* Cw    = (const float*)d_in[1];
    const float* scale = (const float*)d_in[2];
    float* E = (float*)d_out;

    cudaFuncSetAttribute(fused_kernel,
                         cudaFuncAttributeMaxDynamicSharedMemorySize, SMF_BYTES);

    zero_kernel<<<1024, 256>>>(E);
    fused_kernel<<<dim3(NPIX / 1024, BD), 256, SMF_BYTES>>>(X, Cw, scale, E);
    finalize_kernel<<<1024, 256>>>(Cw, E);
}

// round 16
// speedup vs baseline: 7.2929x; 1.0466x over previous
#include <cuda_runtime.h>
#include <math.h>

// Problem constants: B=16, D=256, K=64, H=W=96 -> N=9216
#define BD   16
#define DD   256
#define KK   64
#define NPIX 9216

__device__ float g_sumA[BD * KK];

// ---- tf32 / mma / ldmatrix / cp.async helpers ------------------------------
__device__ __forceinline__ unsigned int f2tf32(float x) {
    unsigned int u;
    asm("cvt.rna.tf32.f32 %0, %1;" : "=r"(u) : "f"(x));
    return u;
}
// NOTE: tf32 operands are fp32-bit-compatible; raw fp32 words fed to the MMA
// are truncated (RZ on low mantissa bits) by the tensor core. We exploit this
// for the hot paths (X operands) and keep RNA cvt only for C and W staging.
__device__ __forceinline__ void mma_tf32(float* c, const unsigned int* a,
                                         const unsigned int* b) {
    asm("mma.sync.aligned.m16n8k8.row.col.f32.tf32.tf32.f32 "
        "{%0,%1,%2,%3}, {%4,%5,%6,%7}, {%8,%9}, {%0,%1,%2,%3};"
        : "+f"(c[0]), "+f"(c[1]), "+f"(c[2]), "+f"(c[3])
        : "r"(a[0]), "r"(a[1]), "r"(a[2]), "r"(a[3]), "r"(b[0]), "r"(b[1]));
}
#define LDSM4(r0, r1, r2, r3, addr)                                          \
    asm volatile("ldmatrix.sync.aligned.m8n8.x4.shared.b16 {%0,%1,%2,%3}, [%4];" \
                 : "=r"(r0), "=r"(r1), "=r"(r2), "=r"(r3) : "r"(addr))
__device__ __forceinline__ void cp16(unsigned int saddr, const void* g) {
    asm volatile("cp.async.cg.shared.global [%0], [%1], 16;"
                 :: "r"(saddr), "l"(g));
}
#define CP_COMMIT() asm volatile("cp.async.commit_group;" ::: "memory")
#define CP_WAIT0()  asm volatile("cp.async.wait_group 0;"  ::: "memory")

// ---------------------------------------------------------------------------
// Kernel 0: zero output + g_sumA (float4)
// ---------------------------------------------------------------------------
__global__ void zero_kernel(float4* __restrict__ E4) {
    int i = blockIdx.x * 256 + threadIdx.x;   // 65536 float4 = 262144 floats
    E4[i] = make_float4(0.f, 0.f, 0.f, 0.f);
    if (i < BD * KK) g_sumA[i] = 0.0f;
}

// ---------------------------------------------------------------------------
// Fused kernel. SMEM word offsets:
//   CS  0     : C tf32 [64][260]              (16640)
//   XS0 16640 : X raw fp32 [256][64] swz      (16384)  } double
//   XS1 33024 : X raw fp32 [256][64] swz      (16384)  } buffer
//   WS  49408 : W tf32 [64 k][68 n]           (4352)
//   SC 53760 [64], C2 53824 [64], RMS 53888 [2][64]x2 = 256, SA 54144 [64]
// total 54208 words = 216832 B -> occupancy 1
// ---------------------------------------------------------------------------
#define CS_OFF   0
#define XS0_OFF  16640
#define XSBUF    16384
#define WS_OFF   49408
#define SC_OFF   53760
#define C2_OFF   53824
#define RMS_OFF  53888
#define SA_OFF   54144
#define SMF_BYTES (54208 * 4)

__global__ void __launch_bounds__(256, 1)
fused_kernel(const float* __restrict__ X, const float* __restrict__ Cw,
             const float* __restrict__ scale, float* __restrict__ E) {
    extern __shared__ float sm[];
    unsigned int* smU = reinterpret_cast<unsigned int*>(sm);
    unsigned int smb;
    asm("{ .reg .u64 t; cvta.to.shared.u64 t, %1; cvt.u32.u64 %0, t; }"
        : "=r"(smb) : "l"(sm));

    const int t = threadIdx.x, lane = t & 31, wp = t >> 5;
    const int g = lane >> 2, tg = lane & 3;
    const int b = blockIdx.y;
    const int gn0 = blockIdx.x << 10;

    const int n0w1 = (wp & 3) << 4, k0w1 = (wp >> 2) << 5, kh = wp >> 2;
    const int k0w2 = (wp & 1) << 5, d0w2 = (wp >> 1) << 6;

    const float* Xg = X + (size_t)b * DD * NPIX + gn0;
    float* Eb = E + (size_t)b * KK * DD;

    // staging geometry: thread t owns n-group gi4 = (t&15)*4, rows d = t>>4 + 16i
    const int gi4 = (t & 15) << 2;
    const int db0 = t >> 4;

    // ---- prologue: kick off chunk 0 copy immediately ----
    {
        #pragma unroll
        for (int i = 0; i < 16; ++i) {
            int d = db0 + (i << 4);
            cp16(smb + 4u * (XS0_OFF + ((d << 6) |
                      (gi4 ^ (((d & 7) << 3) | (d & 4))))),
                 Xg + (size_t)d * NPIX + gi4);
        }
        CP_COMMIT();
    }

    // ---- stage C (tf32 RNA) + scale; zero smem sumA (overlaps G0) ----
    #pragma unroll 4
    for (int i = 0; i < 64; ++i) {
        int idx = t + (i << 8);
        int k = idx >> 8, d = idx & 255;
        smU[CS_OFF + k * 260 + d] = f2tf32(Cw[idx]);
    }
    if (t < 64) { sm[SC_OFF + t] = scale[t]; sm[SA_OFF + t] = 0.0f; }
    __syncthreads();
    if (t < 64) {
        float s = 0.0f;
        #pragma unroll 8
        for (int d = 0; d < 256; ++d) {
            float c = __uint_as_float(smU[CS_OFF + t * 260 + d]);
            s += c * c;
        }
        sm[C2_OFF + t] = s;
    }

    float scv[4][2], c2v[4][2];
    __syncthreads();
    #pragma unroll
    for (int kt = 0; kt < 4; ++kt)
        #pragma unroll
        for (int j = 0; j < 2; ++j) {
            int k = k0w1 + (kt << 3) + (tg << 1) + j;
            scv[kt][j] = sm[SC_OFF + k];
            c2v[kt][j] = sm[C2_OFF + k];
        }

    // ---- fragment address precomputes ----
    int nxA[2][2];
    const int dA0 = tg, dA1 = tg + 4;
    #pragma unroll
    for (int i2 = 0; i2 < 2; ++i2) {
        int d = tg + (i2 << 2);
        int perm = ((d & 7) << 3) | (d & 4);
        #pragma unroll
        for (int i1 = 0; i1 < 2; ++i1)
            nxA[i2][i1] = (n0w1 + g + (i1 << 3)) ^ perm;
    }
    const unsigned int b1_base = smb +
        4u * (CS_OFF + (k0w1 + (((lane >> 4) & 1) << 3) + (lane & 7)) * 260
              + (((lane >> 3) & 1) << 2));
    const unsigned int a2_base = smb +
        4u * (WS_OFF + (k0w2 + (((lane >> 3) & 1) << 3) + (lane & 7)) * 68
              + (((lane >> 4) & 1) << 2));
    const int rB = lane & 7;
    const int permB = (rB << 3) | (rB & 4);
    const int jB4 = ((lane >> 3) & 1) << 2;
    unsigned int b2_row[4];
    #pragma unroll
    for (int q = 0; q < 4; ++q)
        b2_row[q] = 4u * (unsigned)(((d0w2 + (((q << 1) + ((lane >> 4) & 1)) << 3)
                                      + rB) << 6));

    float accE[2][8][4];
    #pragma unroll
    for (int m = 0; m < 2; ++m)
        #pragma unroll
        for (int dt = 0; dt < 8; ++dt)
            #pragma unroll
            for (int j = 0; j < 4; ++j) accE[m][dt][j] = 0.0f;
    float sk[4][2] = {{0.f,0.f},{0.f,0.f},{0.f,0.f},{0.f,0.f}};

    for (int ch = 0; ch < 16; ++ch) {
        const int cur = ch & 1;
        const int xsO = XS0_OFF + (cur ? XSBUF : 0);
        const unsigned int xsB = smb + 4u * xsO;

        CP_WAIT0();                 // this thread's chunk-ch copies done
        __syncthreads();            // all threads' copies visible; prev readers done

        // ---- issue chunk ch+1 into the other buffer (hides under MMAs) ----
        if (ch < 15) {
            const int n1 = (ch + 1) << 6;
            const int oO = XS0_OFF + (cur ? 0 : XSBUF);
            #pragma unroll
            for (int i = 0; i < 16; ++i) {
                int d = db0 + (i << 4);
                cp16(smb + 4u * (oO + ((d << 6) |
                          (gi4 ^ (((d & 7) << 3) | (d & 4))))),
                     Xg + (size_t)d * NPIX + n1 + gi4);
            }
            CP_COMMIT();
        }

        // ---- MMA1: S[64n x 64k], K = 256 ; raw fp32 fed as tf32 (RZ) ----
        float acc1[4][4];
        #pragma unroll
        for (int kt = 0; kt < 4; ++kt)
            #pragma unroll
            for (int j = 0; j < 4; ++j) acc1[kt][j] = 0.0f;
        float x2p0 = 0.0f, x2p1 = 0.0f;
        #pragma unroll
        for (int dd = 0; dd < 256; dd += 8) {
            unsigned int afr[4], bfr[4][2];
            afr[0] = smU[xsO + ((dd + dA0) << 6) + nxA[0][0]];
            afr[1] = smU[xsO + ((dd + dA0) << 6) + nxA[0][1]];
            afr[2] = smU[xsO + ((dd + dA1) << 6) + nxA[1][0]];
            afr[3] = smU[xsO + ((dd + dA1) << 6) + nxA[1][1]];
            float a0 = __uint_as_float(afr[0]), a1 = __uint_as_float(afr[1]);
            float a2 = __uint_as_float(afr[2]), a3 = __uint_as_float(afr[3]);
            x2p0 += a0 * a0 + a2 * a2;
            x2p1 += a1 * a1 + a3 * a3;
            LDSM4(bfr[0][0], bfr[0][1], bfr[1][0], bfr[1][1], b1_base + 4u * dd);
            LDSM4(bfr[2][0], bfr[2][1], bfr[3][0], bfr[3][1],
                  b1_base + 4u * dd + 4u * 16 * 260);
            #pragma unroll
            for (int kt = 0; kt < 4; ++kt) mma_tf32(acc1[kt], afr, bfr[kt]);
        }
        // exact x2: reduce over tg (lanes ^1, ^2 share g => same n rows)
        x2p0 += __shfl_xor_sync(~0u, x2p0, 1);
        x2p0 += __shfl_xor_sync(~0u, x2p0, 2);
        x2p1 += __shfl_xor_sync(~0u, x2p1, 1);
        x2p1 += __shfl_xor_sync(~0u, x2p1, 2);

        // ---- logits + online softmax (single cross-half exchange) ----
        const int r0 = n0w1 + g, r1 = r0 + 8;
        float rm0 = -1e30f, rm1 = -1e30f;
        #pragma unroll
        for (int kt = 0; kt < 4; ++kt)
            #pragma unroll
            for (int j = 0; j < 4; ++j) {
                float x2 = (j & 2) ? x2p1 : x2p0;
                float l = scv[kt][j & 1] * (x2 - 2.0f * acc1[kt][j] + c2v[kt][j & 1]);
                acc1[kt][j] = l;
                if (j & 2) rm1 = fmaxf(rm1, l); else rm0 = fmaxf(rm0, l);
            }
        rm0 = fmaxf(rm0, __shfl_xor_sync(~0u, rm0, 1));
        rm0 = fmaxf(rm0, __shfl_xor_sync(~0u, rm0, 2));
        rm1 = fmaxf(rm1, __shfl_xor_sync(~0u, rm1, 1));
        rm1 = fmaxf(rm1, __shfl_xor_sync(~0u, rm1, 2));
        float rs0 = 0.0f, rs1 = 0.0f;
        #pragma unroll
        for (int kt = 0; kt < 4; ++kt)
            #pragma unroll
            for (int j = 0; j < 4; ++j) {
                float e = __expf(acc1[kt][j] - ((j & 2) ? rm1 : rm0));
                acc1[kt][j] = e;
                if (j & 2) rs1 += e; else rs0 += e;
            }
        rs0 += __shfl_xor_sync(~0u, rs0, 1);
        rs0 += __shfl_xor_sync(~0u, rs0, 2);
        rs1 += __shfl_xor_sync(~0u, rs1, 1);
        rs1 += __shfl_xor_sync(~0u, rs1, 2);
        if (tg == 0) {
            *reinterpret_cast<float2*>(&sm[RMS_OFF + ((kh << 6) + r0) * 2]) =
                make_float2(rm0, rs0);
            *reinterpret_cast<float2*>(&sm[RMS_OFF + ((kh << 6) + r1) * 2]) =
                make_float2(rm1, rs1);
        }
        __syncthreads();
        float2 o0 = *reinterpret_cast<float2*>(
            &sm[RMS_OFF + (((1 - kh) << 6) + r0) * 2]);
        float2 o1 = *reinterpret_cast<float2*>(
            &sm[RMS_OFF + (((1 - kh) << 6) + r1) * 2]);
        float M0 = fmaxf(rm0, o0.x), M1 = fmaxf(rm1, o1.x);
        float tot0 = rs0 * __expf(rm0 - M0) + o0.y * __expf(o0.x - M0);
        float tot1 = rs1 * __expf(rm1 - M1) + o1.y * __expf(o1.x - M1);
        float f0 = __expf(rm0 - M0) / tot0;
        float f1 = __expf(rm1 - M1) / tot1;

        // ---- W -> smem [k][68] (tf32 RNA; cheap, keeps W accurate) ----
        const int kc = k0w1 + (tg << 1);
        #pragma unroll
        for (int kt = 0; kt < 4; ++kt) {
            float w0 = acc1[kt][0] * f0, w1 = acc1[kt][1] * f0;
            float w2 = acc1[kt][2] * f1, w3 = acc1[kt][3] * f1;
            sk[kt][0] += w0 + w2;
            sk[kt][1] += w1 + w3;
            int kr = kc + (kt << 3);
            smU[WS_OFF + kr * 68 + r0]       = f2tf32(w0);
            smU[WS_OFF + (kr + 1) * 68 + r0] = f2tf32(w1);
            smU[WS_OFF + kr * 68 + r1]       = f2tf32(w2);
            smU[WS_OFF + (kr + 1) * 68 + r1] = f2tf32(w3);
        }
        __syncthreads();

        // ---- MMA2: accE += W^T (64k x 64n) * X (64n x 256d) ----
        // X B-frags fed raw (fp32 bits -> tf32 truncation), no cvt.
        #pragma unroll
        for (int ns = 0; ns < 64; ns += 8) {
            unsigned int a2[2][4], b2[8][2];
            LDSM4(a2[0][0], a2[0][1], a2[0][2], a2[0][3], a2_base + 4u * ns);
            LDSM4(a2[1][0], a2[1][1], a2[1][2], a2[1][3],
                  a2_base + 4u * ns + 4u * 16 * 68);
            const unsigned int nsx = 4u * (unsigned)((ns | jB4) ^ permB);
            #pragma unroll
            for (int q = 0; q < 4; ++q)
                LDSM4(b2[2 * q][0], b2[2 * q][1], b2[2 * q + 1][0],
                      b2[2 * q + 1][1], xsB + b2_row[q] + nsx);
            #pragma unroll
            for (int m = 0; m < 2; ++m)
                #pragma unroll
                for (int dt = 0; dt < 8; ++dt)
                    mma_tf32(accE[m][dt], a2[m], b2[dt]);
        }
    }

    // ---- sumA: butterfly over g, commit via smem + one global atomic ----
    #pragma unroll
    for (int kt = 0; kt < 4; ++kt)
        #pragma unroll
        for (int j = 0; j < 2; ++j) {
            float v = sk[kt][j];
            v += __shfl_xor_sync(~0u, v, 4);
            v += __shfl_xor_sync(~0u, v, 8);
            v += __shfl_xor_sync(~0u, v, 16);
            if (lane < 4)
                atomicAdd(&sm[SA_OFF + k0w1 + (kt << 3) + (tg << 1) + j], v);
        }
    __syncthreads();
    if (t < 64) atomicAdd(&g_sumA[(b << 6) + t], sm[SA_OFF + t]);

    // ---- commit register E tile (one atomic pass) ----
    #pragma unroll
    for (int m = 0; m < 2; ++m)
        #pragma unroll
        for (int dt = 0; dt < 8; ++dt)
            #pragma unroll
            for (int j = 0; j < 4; ++j) {
                int k = k0w2 + (m << 4) + g + ((j >> 1) << 3);
                int d = d0w2 + (dt << 3) + (tg << 1) + (j & 1);
                atomicAdd(&Eb[(size_t)k * DD + d], accE[m][dt][j]);
            }
}

// ---------------------------------------------------------------------------
// Finalize: E[b,k,d] -= sumA[b,k] * C[k,d]   (exact fp32, float4)
// ---------------------------------------------------------------------------
__global__ void finalize_kernel(const float4* __restrict__ Cw4,
                                float4* __restrict__ E4) {
    int i4 = blockIdx.x * 256 + threadIdx.x;   // 65536 float4
    int kd4 = i4 & ((KK * DD / 4) - 1);        // k*64 + d4
    int b   = i4 >> 12;
    float s = g_sumA[(b << 6) + (kd4 >> 6)];
    float4 c = Cw4[kd4];
    float4 e = E4[i4];
    e.x -= s * c.x; e.y -= s * c.y; e.z -= s * c.z; e.w -= s * c.w;
    E4[i4] = e;
}

// ---------------------------------------------------------------------------
extern "C" void kernel_launch(void* const* d_in, const int* in_sizes, int n_in,
                              void* d_out, int out_size) {
    const float* X     = (const float*)d_in[0];
    const float* Cw    = (const float*)d_in[1];
    const float* scale = (const float*)d_in[2];
    float* E = (float*)d_out;

    cudaFuncSetAttribute(fused_kernel,
                         cudaFuncAttributeMaxDynamicSharedMemorySize, SMF_BYTES);

    zero_kernel<<<256, 256>>>((float4*)E);
    fused_kernel<<<dim3(NPIX / 1024, BD), 256, SMF_BYTES>>>(X, Cw, scale, E);
    finalize_kernel<<<256, 256>>>((const float4*)Cw, (float4*)E);
}